// round 14
// baseline (speedup 1.0000x reference)
#include <cuda_runtime.h>
#include <cuda_fp16.h>
#include <math.h>
#include <stdint.h>

// ---------------- problem constants ----------------
constexpr int cL  = 12;
constexpr int cD  = 1024;
constexpr int cH  = 16;
constexpr int cDH = 64;
constexpr int cFF = 4096;
constexpr int cV  = 32000;
constexpr int cS  = 1024;
constexpr int cB  = 2;
constexpr int cT  = cB * cS;     // 2048 tokens
constexpr float cEPS = 1e-5f;

// weight-split buffer layout (concatenated, QKV packed per layer as [K=1024][N=3072])
constexpr size_t QKV_PL = (size_t)cD * 3 * cD;
constexpr size_t W1_PL  = (size_t)cD * cFF;
constexpr size_t W2_PL  = (size_t)cFF * cD;
constexpr size_t OFF_QKV = 0;
constexpr size_t OFF_W1  = (size_t)cL * QKV_PL;
constexpr size_t OFF_W2  = OFF_W1 + (size_t)cL * W1_PL;
constexpr size_t OFF_LM  = OFF_W2 + (size_t)cL * W2_PL;
constexpr size_t WTOT    = OFF_LM + (size_t)cD * cV;

// ---------------- scratch (device globals; no allocation allowed) ----------------
__device__ float g_h [cT * cD];
__device__ float g_t [cT * cD];
__device__ unsigned short g_wh[WTOT];          // weights hi (fp16 bits)
__device__ unsigned short g_wl[WTOT];          // weights lo (fp16 bits)
__device__ unsigned short g_ah[cT * cD];
__device__ unsigned short g_al[cT * cD];
__device__ unsigned short g_fh[cT * cFF];
__device__ unsigned short g_fl[cT * cFF];
__device__ unsigned short g_qh[cT * cD];
__device__ unsigned short g_ql[cT * cD];
__device__ unsigned short g_kh[cT * cD];
__device__ unsigned short g_kl[cT * cD];
__device__ unsigned short g_vh[cT * cD];
__device__ unsigned short g_vl[cT * cD];

// ================= PTX helpers =================
__device__ __forceinline__ uint32_t smem_u32(const void* p) {
    uint32_t a;
    asm("{ .reg .u64 t; cvta.to.shared.u64 t, %1; cvt.u32.u64 %0, t; }" : "=r"(a) : "l"(p));
    return a;
}
#define CPA16(smem, g) \
    asm volatile("cp.async.cg.shared.global [%0], [%1], 16;" \
        :: "r"(smem), "l"(__cvta_generic_to_global((const void*)(g))) : "memory")
#define CP_COMMIT() asm volatile("cp.async.commit_group;" ::: "memory")
#define CP_WAIT(n)  asm volatile("cp.async.wait_group %0;" :: "n"(n) : "memory")

__device__ __forceinline__ void ldsm_x4(uint32_t* r, uint32_t addr) {
    asm volatile("ldmatrix.sync.aligned.m8n8.x4.shared.b16 {%0,%1,%2,%3}, [%4];"
        : "=r"(r[0]), "=r"(r[1]), "=r"(r[2]), "=r"(r[3]) : "r"(addr));
}
__device__ __forceinline__ void ldsm_x4_t(uint32_t* r, uint32_t addr) {
    asm volatile("ldmatrix.sync.aligned.m8n8.x4.trans.shared.b16 {%0,%1,%2,%3}, [%4];"
        : "=r"(r[0]), "=r"(r[1]), "=r"(r[2]), "=r"(r[3]) : "r"(addr));
}
// fp16 inputs, fp32 accumulator
__device__ __forceinline__ void mma_hf(float* c, const uint32_t* a, uint32_t b0, uint32_t b1) {
    asm volatile(
        "mma.sync.aligned.m16n8k16.row.col.f32.f16.f16.f32 "
        "{%0,%1,%2,%3}, {%4,%5,%6,%7}, {%8,%9}, {%0,%1,%2,%3};"
        : "+f"(c[0]), "+f"(c[1]), "+f"(c[2]), "+f"(c[3])
        : "r"(a[0]), "r"(a[1]), "r"(a[2]), "r"(a[3]), "r"(b0), "r"(b1));
}
__device__ __forceinline__ void split1(float x, unsigned short& h, unsigned short& l) {
    __half hb = __float2half_rn(x);
    __half lb = __float2half_rn(x - __half2float(hb));
    h = __half_as_ushort(hb);
    l = __half_as_ushort(lb);
}

// ---------------- split fp32 -> hi/lo fp16 (weights) ----------------
__global__ void k_split(const float* __restrict__ src, unsigned short* __restrict__ hi,
                        unsigned short* __restrict__ lo, int n4) {
    int i = blockIdx.x * blockDim.x + threadIdx.x;
    if (i >= n4) return;
    float4 v = ((const float4*)src)[i];
    float f[4] = {v.x, v.y, v.z, v.w};
    unsigned short hs[4], ls[4];
    #pragma unroll
    for (int j = 0; j < 4; j++) split1(f[j], hs[j], ls[j]);
    ushort4 h, l;
    h.x = hs[0]; h.y = hs[1]; h.z = hs[2]; h.w = hs[3];
    l.x = ls[0]; l.y = ls[1]; l.z = ls[2]; l.w = ls[3];
    ((ushort4*)hi)[i] = h;
    ((ushort4*)lo)[i] = l;
}

__global__ void k_split_qkv(const float* __restrict__ wq, const float* __restrict__ wk,
                            const float* __restrict__ wv,
                            unsigned short* __restrict__ hi, unsigned short* __restrict__ lo) {
    int i = blockIdx.x * blockDim.x + threadIdx.x;
    if (i >= (int)(cL * (size_t)cD * cD / 4)) return;
    int l = i >> 18;
    int rem = i & 0x3FFFF;
    int kk = rem >> 8;
    int n4 = rem & 255;
    size_t dbase = (size_t)l * (QKV_PL / 4) + (size_t)kk * 768 + n4;
    const float* srcs[3] = {wq, wk, wv};
    #pragma unroll
    for (int sel = 0; sel < 3; sel++) {
        float4 v = ((const float4*)srcs[sel])[i];
        float f[4] = {v.x, v.y, v.z, v.w};
        unsigned short hs[4], ls[4];
        #pragma unroll
        for (int j = 0; j < 4; j++) split1(f[j], hs[j], ls[j]);
        ushort4 h, lw;
        h.x = hs[0]; h.y = hs[1]; h.z = hs[2]; h.w = hs[3];
        lw.x = ls[0]; lw.y = ls[1]; lw.z = ls[2]; lw.w = ls[3];
        ((ushort4*)hi)[dbase + sel * 256] = h;
        ((ushort4*)lo)[dbase + sel * 256] = lw;
    }
}

// ================= tensor-core GEMM (fp16 3-term, 4 warps, warp tile 64x64) =====
// CTA 128x128x32, 128 threads = 4 warps (2M x 2N), warp tile 64x64.
// EPI: 0 = +bias -> fp32 C, 1 = +bias+gelu -> split Ch0/Cl0, 2 = plain -> fp32 C,
//      4 = QKV fused: output dispatch by n0>>10, out stride 1024
constexpr int A_STRIDE = 40;
constexpr int B_STRIDE = 136;
constexpr int A_SZ  = 128 * A_STRIDE * 2;            // 10240
constexpr int B_SZ  = 32  * B_STRIDE * 2;            // 8704
constexpr int STG   = 2 * A_SZ + 2 * B_SZ;           // 37888
constexpr int MG_SMEM = 3 * STG;                     // 113664 -> 2 CTAs/SM

template <int EPI>
__global__ void __launch_bounds__(128, 2) k_mgemm(
        const unsigned short* __restrict__ Ahg, const unsigned short* __restrict__ Alg,
        const unsigned short* __restrict__ Bhg, const unsigned short* __restrict__ Blg,
        const float* __restrict__ bias0, const float* __restrict__ bias1,
        const float* __restrict__ bias2, float* __restrict__ C,
        unsigned short* __restrict__ Ch0, unsigned short* __restrict__ Cl0,
        unsigned short* __restrict__ Ch1, unsigned short* __restrict__ Cl1,
        unsigned short* __restrict__ Ch2, unsigned short* __restrict__ Cl2,
        int M, int N, int K) {
    extern __shared__ char smem[];
    const uint32_t sb = smem_u32(smem);
    const int tid = threadIdx.x;
    const int lane = tid & 31, wid = tid >> 5;   // 4 warps
    const int wm = (wid >> 1) * 64;              // 0/64
    const int wn = (wid & 1) * 64;               // 0/64
    const int m0 = blockIdx.x * 128, n0 = blockIdx.y * 128;
    const int nch = K >> 5;

    // loaders (128 threads): A row = tid, 32 elems (64B) per limb; B row = tid>>2, 32 elems per quarter
    const int ar = tid;
    const int br = tid >> 2;
    const int bseg = (tid & 3) * 32;             // elem offset within 128-col row

    auto issue = [&](int c) {
        const int st = c % 3;
        const int k0 = c << 5;
        const uint32_t s = sb + st * STG;
        {
            const size_t g = (size_t)(m0 + ar) * K + k0;
            const uint32_t d = s + (uint32_t)(ar * A_STRIDE) * 2;
            #pragma unroll
            for (int j = 0; j < 4; j++) {
                CPA16(d + j * 16,        Ahg + g + j * 8);
                CPA16(d + A_SZ + j * 16, Alg + g + j * 8);
            }
        }
        {
            const size_t g = (size_t)(k0 + br) * N + n0 + bseg;
            const uint32_t d = s + 2 * A_SZ + (uint32_t)(br * B_STRIDE + bseg) * 2;
            #pragma unroll
            for (int j = 0; j < 4; j++) {
                CPA16(d + j * 16,        Bhg + g + j * 8);
                CPA16(d + B_SZ + j * 16, Blg + g + j * 8);
            }
        }
    };

    const int alr = (lane & 7) + ((lane >> 3) & 1) * 8;
    const int alc = (lane >> 4) * 8;
    const uint32_t a_lane = (uint32_t)(alr * A_STRIDE + alc) * 2;
    const int bkr = ((lane >> 4) & 1) * 8 + (lane & 7);
    const int bnc = ((lane >> 3) & 1) * 8;
    const uint32_t b_lane = (uint32_t)(bkr * B_STRIDE + bnc) * 2;

    float acc[4][8][4] = {};   // 4 m-tiles x 8 n-units x 4

    issue(0); CP_COMMIT();
    issue(1); CP_COMMIT();

    for (int c = 0; c < nch; c++) {
        if (c + 1 < nch) CP_WAIT(1);
        else             CP_WAIT(0);
        __syncthreads();
        if (c + 2 < nch) { issue(c + 2); CP_COMMIT(); }

        const uint32_t s  = sb + (c % 3) * STG;
        const uint32_t ah_b = s + (uint32_t)(wm * A_STRIDE) * 2 + a_lane;
        const uint32_t al_b = ah_b + A_SZ;
        const uint32_t bh_b = s + 2 * A_SZ + (uint32_t)wn * 2 + b_lane;
        const uint32_t bl_b = bh_b + B_SZ;

        #pragma unroll
        for (int ks = 0; ks < 2; ks++) {
            const uint32_t ak = (uint32_t)(ks * 16) * 2;
            const uint32_t bk = (uint32_t)(ks * 16 * B_STRIDE) * 2;

            uint32_t ah[4][4];
            #pragma unroll
            for (int mt = 0; mt < 4; mt++)
                ldsm_x4(ah[mt], ah_b + ak + (uint32_t)(mt * 16 * A_STRIDE) * 2);
            uint32_t bh0[8], bh1[8], bl0[8], bl1[8];
            #pragma unroll
            for (int p = 0; p < 4; p++) {
                uint32_t r[4];
                ldsm_x4_t(r, bh_b + bk + (uint32_t)(p * 16) * 2);
                bh0[p * 2] = r[0]; bh0[p * 2 + 1] = r[1];
                bh1[p * 2] = r[2]; bh1[p * 2 + 1] = r[3];
                uint32_t r2[4];
                ldsm_x4_t(r2, bl_b + bk + (uint32_t)(p * 16) * 2);
                bl0[p * 2] = r2[0]; bl0[p * 2 + 1] = r2[1];
                bl1[p * 2] = r2[2]; bl1[p * 2 + 1] = r2[3];
            }

            // Ah * Bh
            #pragma unroll
            for (int mt = 0; mt < 4; mt++)
                #pragma unroll
                for (int nt = 0; nt < 8; nt++)
                    mma_hf(acc[mt][nt], ah[mt], bh0[nt], bh1[nt]);
            // Ah * Bl
            #pragma unroll
            for (int mt = 0; mt < 4; mt++)
                #pragma unroll
                for (int nt = 0; nt < 8; nt++)
                    mma_hf(acc[mt][nt], ah[mt], bl0[nt], bl1[nt]);
            // Al * Bh
            #pragma unroll
            for (int mt = 0; mt < 4; mt++) {
                uint32_t al[4];
                ldsm_x4(al, al_b + ak + (uint32_t)(mt * 16 * A_STRIDE) * 2);
                #pragma unroll
                for (int nt = 0; nt < 8; nt++)
                    mma_hf(acc[mt][nt], al, bh0[nt], bh1[nt]);
            }
        }
    }

    // ---- epilogue ----
    const int erow = lane >> 2;
    const int ecol = (lane & 3) * 2;

    const float* bias = bias0;
    unsigned short* OH = Ch0;
    unsigned short* OL = Cl0;
    int outN = N, nbase = n0;
    if (EPI == 4) {
        const int sel = n0 >> 10;
        bias = (sel == 0) ? bias0 : ((sel == 1) ? bias1 : bias2);
        OH   = (sel == 0) ? Ch0   : ((sel == 1) ? Ch1   : Ch2);
        OL   = (sel == 0) ? Cl0   : ((sel == 1) ? Cl1   : Cl2);
        outN = 1024;
        nbase = n0 & 1023;
    }

    #pragma unroll
    for (int mt = 0; mt < 4; mt++) {
        #pragma unroll
        for (int nt = 0; nt < 8; nt++) {
            const int row = m0 + wm + mt * 16 + erow;
            const int col = nbase + wn + nt * 8 + ecol;
            float v[4] = {acc[mt][nt][0], acc[mt][nt][1], acc[mt][nt][2], acc[mt][nt][3]};
            if (EPI != 2) {
                float b0 = bias[col], b1 = bias[col + 1];
                v[0] += b0; v[1] += b1; v[2] += b0; v[3] += b1;
            }
            if (EPI == 1) {
                #pragma unroll
                for (int j = 0; j < 4; j++)
                    v[j] = 0.5f * v[j] * (1.0f + erff(v[j] * 0.70710678118654752f));
            }
            if (EPI == 0 || EPI == 2) {
                float2 w0; w0.x = v[0]; w0.y = v[1];
                float2 w1; w1.x = v[2]; w1.y = v[3];
                *(float2*)(C + (size_t)row * outN + col)       = w0;
                *(float2*)(C + (size_t)(row + 8) * outN + col) = w1;
            } else {
                unsigned short hs[4], ls[4];
                #pragma unroll
                for (int j = 0; j < 4; j++) split1(v[j], hs[j], ls[j]);
                ushort2 h0, h1, l0, l1;
                h0.x = hs[0]; h0.y = hs[1]; h1.x = hs[2]; h1.y = hs[3];
                l0.x = ls[0]; l0.y = ls[1]; l1.x = ls[2]; l1.y = ls[3];
                *(ushort2*)(OH + (size_t)row * outN + col)       = h0;
                *(ushort2*)(OH + (size_t)(row + 8) * outN + col) = h1;
                *(ushort2*)(OL + (size_t)row * outN + col)       = l0;
                *(ushort2*)(OL + (size_t)(row + 8) * outN + col) = l1;
            }
        }
    }
}

// ================= fused flash attention (fp16 3-term, fp32 acc) ==========
constexpr int FLS    = 72;
constexpr int FL_QL  = 128 * FLS * 2;
constexpr int FL_ST  = 2 * FL_QL;
constexpr int FL_BUF = 64 * FLS * 2;
constexpr int FL_STSZ = 4 * FL_BUF;
constexpr int FL_MS  = FL_ST + 2 * FL_STSZ;
constexpr int FL_SMEM = FL_MS + 2 * 64 * 4;

__global__ void __launch_bounds__(256) k_flash(
        const unsigned short* __restrict__ Qh, const unsigned short* __restrict__ Ql,
        const unsigned short* __restrict__ Kh, const unsigned short* __restrict__ Kl,
        const unsigned short* __restrict__ Vh, const unsigned short* __restrict__ Vl,
        const float* __restrict__ mask, float* __restrict__ out) {
    extern __shared__ char smem[];
    const uint32_t sb = smem_u32(smem);
    const int tid = threadIdx.x, lane = tid & 31, wid = tid >> 5;
    const int qt = blockIdx.x, bh = blockIdx.y, b = bh >> 4, h = bh & 15;
    const size_t qrow0 = (size_t)(b * cS + qt * 128);
    const int colh = h * 64;

    for (int i = tid; i < 1024; i += 256) {
        int r = i >> 3, sg = i & 7;
        size_t g = (qrow0 + r) * cD + colh + sg * 8;
        uint32_t s = sb + (uint32_t)(r * FLS + sg * 8) * 2;
        CPA16(s, Qh + g);
        CPA16(s + FL_QL, Ql + g);
    }
    auto issueKV = [&](int c) {
        int st = c & 1;
        uint32_t base = sb + FL_ST + st * FL_STSZ;
        for (int i = tid; i < 512; i += 256) {
            int r = i >> 3, sg = i & 7;
            size_t g = ((size_t)(b * cS + c * 64 + r)) * cD + colh + sg * 8;
            uint32_t s = base + (uint32_t)(r * FLS + sg * 8) * 2;
            CPA16(s,              Kh + g);
            CPA16(s + FL_BUF,     Kl + g);
            CPA16(s + 2 * FL_BUF, Vh + g);
            CPA16(s + 3 * FL_BUF, Vl + g);
        }
        if (tid < 16)
            CPA16(sb + FL_MS + st * 256 + tid * 16, mask + b * cS + c * 64 + tid * 4);
    };
    issueKV(0); CP_COMMIT();

    const int alr = (lane & 7) + ((lane >> 3) & 1) * 8;
    const int alc = (lane >> 4) * 8;
    const int bkr = ((lane >> 4) & 1) * 8 + (lane & 7);
    const int bnc = ((lane >> 3) & 1) * 8;

    uint32_t qfh[4][4], qfl[4][4];
    float accO[8][4] = {};
    float runm0 = -1e30f, runm1 = -1e30f, runl0 = 0.0f, runl1 = 0.0f;

    for (int c = 0; c < 16; c++) {
        if (c + 1 < 16) { issueKV(c + 1); CP_COMMIT(); CP_WAIT(1); }
        else            { CP_WAIT(0); }
        __syncthreads();
        if (c == 0) {
            uint32_t qb = sb + (uint32_t)((wid * 16 + alr) * FLS + alc) * 2;
            #pragma unroll
            for (int ks = 0; ks < 4; ks++) {
                ldsm_x4(qfh[ks], qb + ks * 32);
                ldsm_x4(qfl[ks], qb + FL_QL + ks * 32);
            }
        }
        const uint32_t kb = sb + FL_ST + (c & 1) * FL_STSZ;

        float S[8][4] = {};
        #pragma unroll
        for (int ks = 0; ks < 4; ks++) {
            #pragma unroll
            for (int np = 0; np < 4; np++) {
                uint32_t off = (uint32_t)((np * 16 + alr) * FLS + ks * 16 + alc) * 2;
                uint32_t rh[4], rl[4];
                ldsm_x4(rh, kb + off);
                ldsm_x4(rl, kb + FL_BUF + off);
                mma_hf(S[2*np],     qfh[ks], rh[0], rh[2]);
                mma_hf(S[2*np + 1], qfh[ks], rh[1], rh[3]);
                mma_hf(S[2*np],     qfh[ks], rl[0], rl[2]);
                mma_hf(S[2*np + 1], qfh[ks], rl[1], rl[3]);
                mma_hf(S[2*np],     qfl[ks], rh[0], rh[2]);
                mma_hf(S[2*np + 1], qfl[ks], rh[1], rh[3]);
            }
        }

        float cm0 = -1e30f, cm1 = -1e30f;
        #pragma unroll
        for (int nt = 0; nt < 8; nt++) {
            float2 m2 = *(float2*)(smem + FL_MS + (c & 1) * 256 + (nt * 8 + (lane & 3) * 2) * 4);
            float b0 = (1.0f - m2.x) * -10000.0f;
            float b1 = (1.0f - m2.y) * -10000.0f;
            S[nt][0] = S[nt][0] * 0.125f + b0;
            S[nt][1] = S[nt][1] * 0.125f + b1;
            S[nt][2] = S[nt][2] * 0.125f + b0;
            S[nt][3] = S[nt][3] * 0.125f + b1;
            cm0 = fmaxf(cm0, fmaxf(S[nt][0], S[nt][1]));
            cm1 = fmaxf(cm1, fmaxf(S[nt][2], S[nt][3]));
        }
        #pragma unroll
        for (int o = 1; o <= 2; o <<= 1) {
            cm0 = fmaxf(cm0, __shfl_xor_sync(0xffffffffu, cm0, o));
            cm1 = fmaxf(cm1, __shfl_xor_sync(0xffffffffu, cm1, o));
        }
        float nm0 = fmaxf(runm0, cm0), nm1 = fmaxf(runm1, cm1);
        float sc0 = __expf(runm0 - nm0), sc1 = __expf(runm1 - nm1);
        float rs0 = 0.0f, rs1 = 0.0f;
        #pragma unroll
        for (int nt = 0; nt < 8; nt++) {
            S[nt][0] = __expf(S[nt][0] - nm0);
            S[nt][1] = __expf(S[nt][1] - nm0);
            S[nt][2] = __expf(S[nt][2] - nm1);
            S[nt][3] = __expf(S[nt][3] - nm1);
            rs0 += S[nt][0] + S[nt][1];
            rs1 += S[nt][2] + S[nt][3];
        }
        #pragma unroll
        for (int o = 1; o <= 2; o <<= 1) {
            rs0 += __shfl_xor_sync(0xffffffffu, rs0, o);
            rs1 += __shfl_xor_sync(0xffffffffu, rs1, o);
        }
        runl0 = runl0 * sc0 + rs0; runl1 = runl1 * sc1 + rs1;
        runm0 = nm0; runm1 = nm1;
        #pragma unroll
        for (int nt = 0; nt < 8; nt++) {
            accO[nt][0] *= sc0; accO[nt][1] *= sc0;
            accO[nt][2] *= sc1; accO[nt][3] *= sc1;
        }

        const uint32_t vb = kb + 2 * FL_BUF;
        #pragma unroll
        for (int ks2 = 0; ks2 < 4; ks2++) {
            uint32_t pah[4], pal[4];
            #pragma unroll
            for (int t = 0; t < 2; t++) {
                #pragma unroll
                for (int pr = 0; pr < 2; pr++) {
                    float x0 = S[2 * ks2 + t][pr * 2 + 0];
                    float x1 = S[2 * ks2 + t][pr * 2 + 1];
                    __half2 hb = __floats2half2_rn(x0, x1);
                    float r0 = x0 - __half2float(__low2half(hb));
                    float r1 = x1 - __half2float(__high2half(hb));
                    __half2 lb = __floats2half2_rn(r0, r1);
                    pah[t * 2 + pr] = *(uint32_t*)&hb;
                    pal[t * 2 + pr] = *(uint32_t*)&lb;
                }
            }
            #pragma unroll
            for (int dp = 0; dp < 4; dp++) {
                uint32_t off = (uint32_t)((ks2 * 16 + bkr) * FLS + dp * 16 + bnc) * 2;
                uint32_t vh4[4], vl4[4];
                ldsm_x4_t(vh4, vb + off);
                ldsm_x4_t(vl4, vb + FL_BUF + off);
                mma_hf(accO[2*dp],     pah, vh4[0], vh4[2]);
                mma_hf(accO[2*dp + 1], pah, vh4[1], vh4[3]);
                mma_hf(accO[2*dp],     pah, vl4[0], vl4[2]);
                mma_hf(accO[2*dp + 1], pah, vl4[1], vl4[3]);
                mma_hf(accO[2*dp],     pal, vh4[0], vh4[2]);
                mma_hf(accO[2*dp + 1], pal, vh4[1], vh4[3]);
            }
        }
        __syncthreads();
    }

    const float inv0 = 1.0f / runl0, inv1 = 1.0f / runl1;
    const size_t row0 = qrow0 + wid * 16 + (lane >> 2);
    #pragma unroll
    for (int nt = 0; nt < 8; nt++) {
        int col = colh + nt * 8 + (lane & 3) * 2;
        float2 w0; w0.x = accO[nt][0] * inv0; w0.y = accO[nt][1] * inv0;
        float2 w1; w1.x = accO[nt][2] * inv1; w1.y = accO[nt][3] * inv1;
        *(float2*)(out + row0 * cD + col)       = w0;
        *(float2*)(out + (row0 + 8) * cD + col) = w1;
    }
}

// ---------------- block reductions ----------------
__device__ __forceinline__ float block_sum(float v, float* sred) {
    #pragma unroll
    for (int o = 16; o > 0; o >>= 1) v += __shfl_xor_sync(0xffffffffu, v, o);
    int lane = threadIdx.x & 31, w = threadIdx.x >> 5;
    if (lane == 0) sred[w] = v;
    __syncthreads();
    if (w == 0) {
        v = (lane < (int)(blockDim.x >> 5)) ? sred[lane] : 0.0f;
        #pragma unroll
        for (int o = 16; o > 0; o >>= 1) v += __shfl_xor_sync(0xffffffffu, v, o);
        if (lane == 0) sred[0] = v;
    }
    __syncthreads();
    float r = sred[0];
    __syncthreads();
    return r;
}

// ---------------- embedding + LN0 (+ split out) ----------------
__global__ void k_embed(const int* __restrict__ ids,
                        const float* __restrict__ te, const float* __restrict__ pe,
                        const float* __restrict__ g,  const float* __restrict__ b,
                        float* __restrict__ out,
                        unsigned short* __restrict__ oh, unsigned short* __restrict__ ol) {
    __shared__ float sred[32];
    int t = blockIdx.x;
    int s = t % cS;
    int id = ids[t];
    int j4 = threadIdx.x;
    float4 a = *(const float4*)(te + (size_t)id * cD + j4 * 4);
    float4 p = *(const float4*)(pe + (size_t)s  * cD + j4 * 4);
    float x0 = a.x + p.x, x1 = a.y + p.y, x2 = a.z + p.z, x3 = a.w + p.w;

    float mu = block_sum(x0 + x1 + x2 + x3, sred) * (1.0f / cD);
    float d0 = x0 - mu, d1 = x1 - mu, d2 = x2 - mu, d3 = x3 - mu;
    float var = block_sum(d0*d0 + d1*d1 + d2*d2 + d3*d3, sred) * (1.0f / cD);
    float rs = rsqrtf(var + cEPS);

    float4 gg = *(const float4*)(g + j4 * 4);
    float4 bb = *(const float4*)(b + j4 * 4);
    float o[4];
    o[0] = d0 * rs * gg.x + bb.x;
    o[1] = d1 * rs * gg.y + bb.y;
    o[2] = d2 * rs * gg.z + bb.z;
    o[3] = d3 * rs * gg.w + bb.w;
    float4 of; of.x = o[0]; of.y = o[1]; of.z = o[2]; of.w = o[3];
    *(float4*)(out + (size_t)t * cD + j4 * 4) = of;
    unsigned short hs[4], ls[4];
    #pragma unroll
    for (int j = 0; j < 4; j++) split1(o[j], hs[j], ls[j]);
    ushort4 hv, lv;
    hv.x = hs[0]; hv.y = hs[1]; hv.z = hs[2]; hv.w = hs[3];
    lv.x = ls[0]; lv.y = ls[1]; lv.z = ls[2]; lv.w = ls[3];
    *(ushort4*)(oh + (size_t)t * cD + j4 * 4) = hv;
    *(ushort4*)(ol + (size_t)t * cD + j4 * 4) = lv;
}

// ---------------- residual add + LN (+ split out) ----------------
__global__ void k_resln(const float* __restrict__ hin, const float* __restrict__ add,
                        const float* __restrict__ g,   const float* __restrict__ b,
                        float* __restrict__ out,
                        unsigned short* __restrict__ oh, unsigned short* __restrict__ ol) {
    __shared__ float sred[32];
    int t = blockIdx.x;
    int j4 = threadIdx.x;
    float4 a = *(const float4*)(hin + (size_t)t * cD + j4 * 4);
    float4 p = *(const float4*)(add + (size_t)t * cD + j4 * 4);
    float x0 = a.x + p.x, x1 = a.y + p.y, x2 = a.z + p.z, x3 = a.w + p.w;

    float mu = block_sum(x0 + x1 + x2 + x3, sred) * (1.0f / cD);
    float d0 = x0 - mu, d1 = x1 - mu, d2 = x2 - mu, d3 = x3 - mu;
    float var = block_sum(d0*d0 + d1*d1 + d2*d2 + d3*d3, sred) * (1.0f / cD);
    float rs = rsqrtf(var + cEPS);

    float4 gg = *(const float4*)(g + j4 * 4);
    float4 bb = *(const float4*)(b + j4 * 4);
    float o[4];
    o[0] = d0 * rs * gg.x + bb.x;
    o[1] = d1 * rs * gg.y + bb.y;
    o[2] = d2 * rs * gg.z + bb.z;
    o[3] = d3 * rs * gg.w + bb.w;
    float4 of; of.x = o[0]; of.y = o[1]; of.z = o[2]; of.w = o[3];
    *(float4*)(out + (size_t)t * cD + j4 * 4) = of;
    unsigned short hs[4], ls[4];
    #pragma unroll
    for (int j = 0; j < 4; j++) split1(o[j], hs[j], ls[j]);
    ushort4 hv, lv;
    hv.x = hs[0]; hv.y = hs[1]; hv.z = hs[2]; hv.w = hs[3];
    lv.x = ls[0]; lv.y = ls[1]; lv.z = ls[2]; lv.w = ls[3];
    *(ushort4*)(oh + (size_t)t * cD + j4 * 4) = hv;
    *(ushort4*)(ol + (size_t)t * cD + j4 * 4) = lv;
}

// ---------------- launch ----------------
extern "C" void kernel_launch(void* const* d_in, const int* in_sizes, int n_in,
                              void* d_out, int out_size) {
    const int*   ids  = (const int*)  d_in[0];
    const float* mask = (const float*)d_in[1];
    const float* te   = (const float*)d_in[2];
    const float* pe   = (const float*)d_in[3];
    const float* ln0g = (const float*)d_in[4];
    const float* ln0b = (const float*)d_in[5];
    const float* Wq   = (const float*)d_in[6];
    const float* bq   = (const float*)d_in[7];
    const float* Wk   = (const float*)d_in[8];
    const float* bk   = (const float*)d_in[9];
    const float* Wv   = (const float*)d_in[10];
    const float* bv   = (const float*)d_in[11];
    const float* ln1g = (const float*)d_in[12];
    const float* ln1b = (const float*)d_in[13];
    const float* W1   = (const float*)d_in[14];
    const float* b1   = (const float*)d_in[15];
    const float* W2   = (const float*)d_in[16];
    const float* b2   = (const float*)d_in[17];
    const float* ln2g = (const float*)d_in[18];
    const float* ln2b = (const float*)d_in[19];
    const float* Wlm  = (const float*)d_in[20];
    float* out = (float*)d_out;

    float *h, *tm;
    unsigned short *wh, *wl, *ah, *al, *fh, *fl, *qh, *ql, *kh, *kl, *vh, *vl;
    cudaGetSymbolAddress((void**)&h,  g_h);
    cudaGetSymbolAddress((void**)&tm, g_t);
    cudaGetSymbolAddress((void**)&wh, g_wh);
    cudaGetSymbolAddress((void**)&wl, g_wl);
    cudaGetSymbolAddress((void**)&ah, g_ah);
    cudaGetSymbolAddress((void**)&al, g_al);
    cudaGetSymbolAddress((void**)&fh, g_fh);
    cudaGetSymbolAddress((void**)&fl, g_fl);
    cudaGetSymbolAddress((void**)&qh, g_qh);
    cudaGetSymbolAddress((void**)&ql, g_ql);
    cudaGetSymbolAddress((void**)&kh, g_kh);
    cudaGetSymbolAddress((void**)&kl, g_kl);
    cudaGetSymbolAddress((void**)&vh, g_vh);
    cudaGetSymbolAddress((void**)&vl, g_vl);

    cudaFuncSetAttribute(k_mgemm<0>, cudaFuncAttributeMaxDynamicSharedMemorySize, MG_SMEM);
    cudaFuncSetAttribute(k_mgemm<1>, cudaFuncAttributeMaxDynamicSharedMemorySize, MG_SMEM);
    cudaFuncSetAttribute(k_mgemm<2>, cudaFuncAttributeMaxDynamicSharedMemorySize, MG_SMEM);
    cudaFuncSetAttribute(k_mgemm<4>, cudaFuncAttributeMaxDynamicSharedMemorySize, MG_SMEM);
    cudaFuncSetAttribute(k_flash,    cudaFuncAttributeMaxDynamicSharedMemorySize, FL_SMEM);

    // ---- weight splits: 4 launches ----
    k_split_qkv<<<(int)(cL * (size_t)cD * cD / 4 / 256), 256>>>(Wq, Wk, Wv, wh + OFF_QKV, wl + OFF_QKV);
    k_split<<<(int)(cL * W1_PL / 4 / 256), 256>>>(W1, wh + OFF_W1, wl + OFF_W1, (int)(cL * W1_PL / 4));
    k_split<<<(int)(cL * W2_PL / 4 / 256), 256>>>(W2, wh + OFF_W2, wl + OFF_W2, (int)(cL * W2_PL / 4));
    k_split<<<(int)((size_t)cD * cV / 4 / 256), 256>>>(Wlm, wh + OFF_LM, wl + OFF_LM, (int)((size_t)cD * cV / 4));

    k_embed<<<cT, 256>>>(ids, te, pe, ln0g, ln0b, h, ah, al);

    for (int l = 0; l < cL; l++) {
        const unsigned short* wqkvh = wh + OFF_QKV + (size_t)l * QKV_PL;
        const unsigned short* wqkvl = wl + OFF_QKV + (size_t)l * QKV_PL;
        const unsigned short* w1h = wh + OFF_W1 + (size_t)l * W1_PL;
        const unsigned short* w1l = wl + OFF_W1 + (size_t)l * W1_PL;
        const unsigned short* w2h = wh + OFF_W2 + (size_t)l * W2_PL;
        const unsigned short* w2l = wl + OFF_W2 + (size_t)l * W2_PL;
        size_t ovb = (size_t)l * cD;
        size_t ob1 = (size_t)l * cFF;

        k_mgemm<4><<<dim3(cT / 128, 3 * cD / 128), 128, MG_SMEM>>>(
            ah, al, wqkvh, wqkvl, bq + ovb, bk + ovb, bv + ovb, nullptr,
            qh, ql, kh, kl, vh, vl, cT, 3 * cD, cD);

        k_flash<<<dim3(cS / 128, cB * cH), 256, FL_SMEM>>>(qh, ql, kh, kl, vh, vl, mask, tm);

        k_resln<<<cT, 256>>>(h, tm, ln1g + ovb, ln1b + ovb, h, ah, al);

        k_mgemm<1><<<dim3(cT / 128, cFF / 128), 128, MG_SMEM>>>(
            ah, al, w1h, w1l, b1 + ob1, nullptr, nullptr, nullptr,
            fh, fl, nullptr, nullptr, nullptr, nullptr, cT, cFF, cD);
        k_mgemm<0><<<dim3(cT / 128, cD / 128), 128, MG_SMEM>>>(
            fh, fl, w2h, w2l, b2 + ovb, nullptr, nullptr, tm,
            nullptr, nullptr, nullptr, nullptr, nullptr, nullptr, cT, cD, cFF);

        k_resln<<<cT, 256>>>(h, tm, ln2g + ovb, ln2b + ovb, h, ah, al);
    }

    k_mgemm<2><<<dim3(cT / 128, cV / 128), 128, MG_SMEM>>>(
        ah, al, wh + OFF_LM, wl + OFF_LM, nullptr, nullptr, nullptr, out,
        nullptr, nullptr, nullptr, nullptr, nullptr, nullptr, cT, cV, cD);
}

// round 15
// speedup vs baseline: 1.2535x; 1.2535x over previous
#include <cuda_runtime.h>
#include <cuda_fp16.h>
#include <math.h>
#include <stdint.h>

// ---------------- problem constants ----------------
constexpr int cL  = 12;
constexpr int cD  = 1024;
constexpr int cH  = 16;
constexpr int cDH = 64;
constexpr int cFF = 4096;
constexpr int cV  = 32000;
constexpr int cS  = 1024;
constexpr int cB  = 2;
constexpr int cT  = cB * cS;     // 2048 tokens
constexpr float cEPS = 1e-5f;

// weight-split buffer layout (concatenated, QKV packed per layer as [K=1024][N=3072])
constexpr size_t QKV_PL = (size_t)cD * 3 * cD;
constexpr size_t W1_PL  = (size_t)cD * cFF;
constexpr size_t W2_PL  = (size_t)cFF * cD;
constexpr size_t OFF_QKV = 0;
constexpr size_t OFF_W1  = (size_t)cL * QKV_PL;
constexpr size_t OFF_W2  = OFF_W1 + (size_t)cL * W1_PL;
constexpr size_t OFF_LM  = OFF_W2 + (size_t)cL * W2_PL;
constexpr size_t WTOT    = OFF_LM + (size_t)cD * cV;

// ---------------- scratch (device globals; no allocation allowed) ----------------
__device__ float g_h [cT * cD];
__device__ float g_t [cT * cD];
__device__ unsigned short g_wh[WTOT];          // weights hi (fp16 bits)
__device__ unsigned short g_wl[WTOT];          // weights lo (fp16 bits)
__device__ unsigned short g_ah[cT * cD];
__device__ unsigned short g_al[cT * cD];
__device__ unsigned short g_fh[cT * cFF];
__device__ unsigned short g_fl[cT * cFF];
__device__ unsigned short g_qh[cT * cD];
__device__ unsigned short g_ql[cT * cD];
__device__ unsigned short g_kh[cT * cD];
__device__ unsigned short g_kl[cT * cD];
__device__ unsigned short g_vh[cT * cD];
__device__ unsigned short g_vl[cT * cD];

// ================= PTX helpers =================
__device__ __forceinline__ uint32_t smem_u32(const void* p) {
    uint32_t a;
    asm("{ .reg .u64 t; cvta.to.shared.u64 t, %1; cvt.u32.u64 %0, t; }" : "=r"(a) : "l"(p));
    return a;
}
#define CPA16(smem, g) \
    asm volatile("cp.async.cg.shared.global [%0], [%1], 16;" \
        :: "r"(smem), "l"(__cvta_generic_to_global((const void*)(g))) : "memory")
#define CP_COMMIT() asm volatile("cp.async.commit_group;" ::: "memory")
#define CP_WAIT(n)  asm volatile("cp.async.wait_group %0;" :: "n"(n) : "memory")

__device__ __forceinline__ void ldsm_x4(uint32_t* r, uint32_t addr) {
    asm volatile("ldmatrix.sync.aligned.m8n8.x4.shared.b16 {%0,%1,%2,%3}, [%4];"
        : "=r"(r[0]), "=r"(r[1]), "=r"(r[2]), "=r"(r[3]) : "r"(addr));
}
__device__ __forceinline__ void ldsm_x4_t(uint32_t* r, uint32_t addr) {
    asm volatile("ldmatrix.sync.aligned.m8n8.x4.trans.shared.b16 {%0,%1,%2,%3}, [%4];"
        : "=r"(r[0]), "=r"(r[1]), "=r"(r[2]), "=r"(r[3]) : "r"(addr));
}
// fp16 inputs, fp32 accumulator
__device__ __forceinline__ void mma_hf(float* c, const uint32_t* a, uint32_t b0, uint32_t b1) {
    asm volatile(
        "mma.sync.aligned.m16n8k16.row.col.f32.f16.f16.f32 "
        "{%0,%1,%2,%3}, {%4,%5,%6,%7}, {%8,%9}, {%0,%1,%2,%3};"
        : "+f"(c[0]), "+f"(c[1]), "+f"(c[2]), "+f"(c[3])
        : "r"(a[0]), "r"(a[1]), "r"(a[2]), "r"(a[3]), "r"(b0), "r"(b1));
}
__device__ __forceinline__ void split1(float x, unsigned short& h, unsigned short& l) {
    __half hb = __float2half_rn(x);
    __half lb = __float2half_rn(x - __half2float(hb));
    h = __half_as_ushort(hb);
    l = __half_as_ushort(lb);
}

// ---------------- split fp32 -> hi/lo fp16 (weights) ----------------
__global__ void k_split(const float* __restrict__ src, unsigned short* __restrict__ hi,
                        unsigned short* __restrict__ lo, int n4) {
    int i = blockIdx.x * blockDim.x + threadIdx.x;
    if (i >= n4) return;
    float4 v = ((const float4*)src)[i];
    float f[4] = {v.x, v.y, v.z, v.w};
    unsigned short hs[4], ls[4];
    #pragma unroll
    for (int j = 0; j < 4; j++) split1(f[j], hs[j], ls[j]);
    ushort4 h, l;
    h.x = hs[0]; h.y = hs[1]; h.z = hs[2]; h.w = hs[3];
    l.x = ls[0]; l.y = ls[1]; l.z = ls[2]; l.w = ls[3];
    ((ushort4*)hi)[i] = h;
    ((ushort4*)lo)[i] = l;
}

__global__ void k_split_qkv(const float* __restrict__ wq, const float* __restrict__ wk,
                            const float* __restrict__ wv,
                            unsigned short* __restrict__ hi, unsigned short* __restrict__ lo) {
    int i = blockIdx.x * blockDim.x + threadIdx.x;
    if (i >= (int)(cL * (size_t)cD * cD / 4)) return;
    int l = i >> 18;
    int rem = i & 0x3FFFF;
    int kk = rem >> 8;
    int n4 = rem & 255;
    size_t dbase = (size_t)l * (QKV_PL / 4) + (size_t)kk * 768 + n4;
    const float* srcs[3] = {wq, wk, wv};
    #pragma unroll
    for (int sel = 0; sel < 3; sel++) {
        float4 v = ((const float4*)srcs[sel])[i];
        float f[4] = {v.x, v.y, v.z, v.w};
        unsigned short hs[4], ls[4];
        #pragma unroll
        for (int j = 0; j < 4; j++) split1(f[j], hs[j], ls[j]);
        ushort4 h, lw;
        h.x = hs[0]; h.y = hs[1]; h.z = hs[2]; h.w = hs[3];
        lw.x = ls[0]; lw.y = ls[1]; lw.z = ls[2]; lw.w = ls[3];
        ((ushort4*)hi)[dbase + sel * 256] = h;
        ((ushort4*)lo)[dbase + sel * 256] = lw;
    }
}

// ================= tensor-core GEMM (fp16 split, R8 structure) =====
// CTA 128x128x32, 256 threads = 8 warps (2M x 4N), warp tile 64x32, 3-stage, 2 CTA/SM.
// TERMS: 3 = AhBh + AhBl + AlBh; 2 = AhBh + AhBl (terminal GEMMs only)
// EPI: 0 = +bias -> fp32 C, 1 = +bias+gelu -> split Ch0/Cl0, 2 = plain -> fp32 C,
//      4 = QKV fused: output dispatch by n0>>10, out stride 1024
constexpr int A_STRIDE = 40;
constexpr int B_STRIDE = 136;
constexpr int A_SZ  = 128 * A_STRIDE * 2;
constexpr int B_SZ  = 32  * B_STRIDE * 2;
constexpr int STG   = 2 * A_SZ + 2 * B_SZ;           // 37888
constexpr int MG_SMEM = 3 * STG;                     // 113664 -> 2 CTAs/SM

template <int EPI, int TERMS>
__global__ void __launch_bounds__(256, 2) k_mgemm(
        const unsigned short* __restrict__ Ahg, const unsigned short* __restrict__ Alg,
        const unsigned short* __restrict__ Bhg, const unsigned short* __restrict__ Blg,
        const float* __restrict__ bias0, const float* __restrict__ bias1,
        const float* __restrict__ bias2, float* __restrict__ C,
        unsigned short* __restrict__ Ch0, unsigned short* __restrict__ Cl0,
        unsigned short* __restrict__ Ch1, unsigned short* __restrict__ Cl1,
        unsigned short* __restrict__ Ch2, unsigned short* __restrict__ Cl2,
        int M, int N, int K) {
    extern __shared__ char smem[];
    const uint32_t sb = smem_u32(smem);
    const int tid = threadIdx.x;
    const int lane = tid & 31, wid = tid >> 5;
    const int wm = (wid >> 2) * 64;
    const int wn = (wid & 3) * 32;
    const int m0 = blockIdx.x * 128, n0 = blockIdx.y * 128;
    const int nch = K >> 5;

    const int ar = tid >> 1;
    const int aseg = (tid & 1) * 16;
    const int br = tid >> 3;
    const int bseg = (tid & 7) * 16;

    auto issue = [&](int c) {
        const int st = c % 3;
        const int k0 = c << 5;
        const uint32_t s = sb + st * STG;
        const size_t ago = (size_t)(m0 + ar) * K + k0 + aseg;
        const size_t bgo = (size_t)(k0 + br) * N + n0 + bseg;
        const uint32_t asm_off = s + (uint32_t)(ar * A_STRIDE + aseg) * 2;
        const uint32_t bsm_off = s + 2 * A_SZ + (uint32_t)(br * B_STRIDE + bseg) * 2;
        #pragma unroll
        for (int j = 0; j < 2; j++) {
            CPA16(asm_off + j * 16,          Ahg + ago + j * 8);
            CPA16(bsm_off + j * 16,          Bhg + bgo + j * 8);
            CPA16(bsm_off + B_SZ + j * 16,   Blg + bgo + j * 8);
            if (TERMS == 3) {
                CPA16(asm_off + A_SZ + j * 16, Alg + ago + j * 8);
            }
        }
    };

    const int alr = (lane & 7) + ((lane >> 3) & 1) * 8;
    const int alc = (lane >> 4) * 8;
    const uint32_t a_lane = (uint32_t)(alr * A_STRIDE + alc) * 2;
    const int bkr = ((lane >> 4) & 1) * 8 + (lane & 7);
    const int bnc = ((lane >> 3) & 1) * 8;
    const uint32_t b_lane = (uint32_t)(bkr * B_STRIDE + bnc) * 2;

    float acc[4][4][4] = {};

    issue(0); CP_COMMIT();
    issue(1); CP_COMMIT();

    for (int c = 0; c < nch; c++) {
        if (c + 1 < nch) CP_WAIT(1);
        else             CP_WAIT(0);
        __syncthreads();
        if (c + 2 < nch) { issue(c + 2); CP_COMMIT(); }

        const uint32_t s  = sb + (c % 3) * STG;
        const uint32_t ah_b = s + (uint32_t)(wm * A_STRIDE) * 2 + a_lane;
        const uint32_t al_b = ah_b + A_SZ;
        const uint32_t bh_b = s + 2 * A_SZ + (uint32_t)wn * 2 + b_lane;
        const uint32_t bl_b = bh_b + B_SZ;

        #pragma unroll
        for (int ks = 0; ks < 2; ks++) {
            const uint32_t ak = (uint32_t)(ks * 16) * 2;
            const uint32_t bk = (uint32_t)(ks * 16 * B_STRIDE) * 2;

            uint32_t ah[4][4];
            #pragma unroll
            for (int mt = 0; mt < 4; mt++)
                ldsm_x4(ah[mt], ah_b + ak + (uint32_t)(mt * 16 * A_STRIDE) * 2);
            uint32_t bh0[4], bh1[4];
            #pragma unroll
            for (int p = 0; p < 2; p++) {
                uint32_t r[4];
                ldsm_x4_t(r, bh_b + bk + (uint32_t)(p * 16) * 2);
                bh0[p * 2] = r[0]; bh0[p * 2 + 1] = r[1];
                bh1[p * 2] = r[2]; bh1[p * 2 + 1] = r[3];
            }
            // Ah * Bh
            #pragma unroll
            for (int mt = 0; mt < 4; mt++)
                #pragma unroll
                for (int nt = 0; nt < 4; nt++)
                    mma_hf(acc[mt][nt], ah[mt], bh0[nt], bh1[nt]);

            // Ah * Bl
            {
                uint32_t bl0[4], bl1[4];
                #pragma unroll
                for (int p = 0; p < 2; p++) {
                    uint32_t r[4];
                    ldsm_x4_t(r, bl_b + bk + (uint32_t)(p * 16) * 2);
                    bl0[p * 2] = r[0]; bl0[p * 2 + 1] = r[1];
                    bl1[p * 2] = r[2]; bl1[p * 2 + 1] = r[3];
                }
                #pragma unroll
                for (int mt = 0; mt < 4; mt++)
                    #pragma unroll
                    for (int nt = 0; nt < 4; nt++)
                        mma_hf(acc[mt][nt], ah[mt], bl0[nt], bl1[nt]);
            }
            // Al * Bh
            if (TERMS == 3) {
                uint32_t al[4];
                #pragma unroll
                for (int mt = 0; mt < 4; mt++) {
                    ldsm_x4(al, al_b + ak + (uint32_t)(mt * 16 * A_STRIDE) * 2);
                    #pragma unroll
                    for (int nt = 0; nt < 4; nt++)
                        mma_hf(acc[mt][nt], al, bh0[nt], bh1[nt]);
                }
            }
        }
    }

    // ---- epilogue ----
    const int erow = lane >> 2;
    const int ecol = (lane & 3) * 2;

    const float* bias = bias0;
    unsigned short* OH = Ch0;
    unsigned short* OL = Cl0;
    int outN = N, nbase = n0;
    if (EPI == 4) {
        const int sel = n0 >> 10;
        bias = (sel == 0) ? bias0 : ((sel == 1) ? bias1 : bias2);
        OH   = (sel == 0) ? Ch0   : ((sel == 1) ? Ch1   : Ch2);
        OL   = (sel == 0) ? Cl0   : ((sel == 1) ? Cl1   : Cl2);
        outN = 1024;
        nbase = n0 & 1023;
    }

    #pragma unroll
    for (int mt = 0; mt < 4; mt++) {
        #pragma unroll
        for (int nt = 0; nt < 4; nt++) {
            const int row = m0 + wm + mt * 16 + erow;
            const int col = nbase + wn + nt * 8 + ecol;
            float v[4] = {acc[mt][nt][0], acc[mt][nt][1], acc[mt][nt][2], acc[mt][nt][3]};
            if (EPI != 2) {
                float b0 = bias[col], b1 = bias[col + 1];
                v[0] += b0; v[1] += b1; v[2] += b0; v[3] += b1;
            }
            if (EPI == 1) {
                #pragma unroll
                for (int j = 0; j < 4; j++)
                    v[j] = 0.5f * v[j] * (1.0f + erff(v[j] * 0.70710678118654752f));
            }
            if (EPI == 0 || EPI == 2) {
                float2 w0; w0.x = v[0]; w0.y = v[1];
                float2 w1; w1.x = v[2]; w1.y = v[3];
                *(float2*)(C + (size_t)row * outN + col)       = w0;
                *(float2*)(C + (size_t)(row + 8) * outN + col) = w1;
            } else {
                unsigned short hs[4], ls[4];
                #pragma unroll
                for (int j = 0; j < 4; j++) split1(v[j], hs[j], ls[j]);
                ushort2 h0, h1, l0, l1;
                h0.x = hs[0]; h0.y = hs[1]; h1.x = hs[2]; h1.y = hs[3];
                l0.x = ls[0]; l0.y = ls[1]; l1.x = ls[2]; l1.y = ls[3];
                *(ushort2*)(OH + (size_t)row * outN + col)       = h0;
                *(ushort2*)(OH + (size_t)(row + 8) * outN + col) = h1;
                *(ushort2*)(OL + (size_t)row * outN + col)       = l0;
                *(ushort2*)(OL + (size_t)(row + 8) * outN + col) = l1;
            }
        }
    }
}

// ================= fused flash attention (fp16 3-term, fp32 acc) ==========
constexpr int FLS    = 72;
constexpr int FL_QL  = 128 * FLS * 2;
constexpr int FL_ST  = 2 * FL_QL;
constexpr int FL_BUF = 64 * FLS * 2;
constexpr int FL_STSZ = 4 * FL_BUF;
constexpr int FL_MS  = FL_ST + 2 * FL_STSZ;
constexpr int FL_SMEM = FL_MS + 2 * 64 * 4;

__global__ void __launch_bounds__(256) k_flash(
        const unsigned short* __restrict__ Qh, const unsigned short* __restrict__ Ql,
        const unsigned short* __restrict__ Kh, const unsigned short* __restrict__ Kl,
        const unsigned short* __restrict__ Vh, const unsigned short* __restrict__ Vl,
        const float* __restrict__ mask, float* __restrict__ out) {
    extern __shared__ char smem[];
    const uint32_t sb = smem_u32(smem);
    const int tid = threadIdx.x, lane = tid & 31, wid = tid >> 5;
    const int qt = blockIdx.x, bh = blockIdx.y, b = bh >> 4, h = bh & 15;
    const size_t qrow0 = (size_t)(b * cS + qt * 128);
    const int colh = h * 64;

    for (int i = tid; i < 1024; i += 256) {
        int r = i >> 3, sg = i & 7;
        size_t g = (qrow0 + r) * cD + colh + sg * 8;
        uint32_t s = sb + (uint32_t)(r * FLS + sg * 8) * 2;
        CPA16(s, Qh + g);
        CPA16(s + FL_QL, Ql + g);
    }
    auto issueKV = [&](int c) {
        int st = c & 1;
        uint32_t base = sb + FL_ST + st * FL_STSZ;
        for (int i = tid; i < 512; i += 256) {
            int r = i >> 3, sg = i & 7;
            size_t g = ((size_t)(b * cS + c * 64 + r)) * cD + colh + sg * 8;
            uint32_t s = base + (uint32_t)(r * FLS + sg * 8) * 2;
            CPA16(s,              Kh + g);
            CPA16(s + FL_BUF,     Kl + g);
            CPA16(s + 2 * FL_BUF, Vh + g);
            CPA16(s + 3 * FL_BUF, Vl + g);
        }
        if (tid < 16)
            CPA16(sb + FL_MS + st * 256 + tid * 16, mask + b * cS + c * 64 + tid * 4);
    };
    issueKV(0); CP_COMMIT();

    const int alr = (lane & 7) + ((lane >> 3) & 1) * 8;
    const int alc = (lane >> 4) * 8;
    const int bkr = ((lane >> 4) & 1) * 8 + (lane & 7);
    const int bnc = ((lane >> 3) & 1) * 8;

    uint32_t qfh[4][4], qfl[4][4];
    float accO[8][4] = {};
    float runm0 = -1e30f, runm1 = -1e30f, runl0 = 0.0f, runl1 = 0.0f;

    for (int c = 0; c < 16; c++) {
        if (c + 1 < 16) { issueKV(c + 1); CP_COMMIT(); CP_WAIT(1); }
        else            { CP_WAIT(0); }
        __syncthreads();
        if (c == 0) {
            uint32_t qb = sb + (uint32_t)((wid * 16 + alr) * FLS + alc) * 2;
            #pragma unroll
            for (int ks = 0; ks < 4; ks++) {
                ldsm_x4(qfh[ks], qb + ks * 32);
                ldsm_x4(qfl[ks], qb + FL_QL + ks * 32);
            }
        }
        const uint32_t kb = sb + FL_ST + (c & 1) * FL_STSZ;

        float S[8][4] = {};
        #pragma unroll
        for (int ks = 0; ks < 4; ks++) {
            #pragma unroll
            for (int np = 0; np < 4; np++) {
                uint32_t off = (uint32_t)((np * 16 + alr) * FLS + ks * 16 + alc) * 2;
                uint32_t rh[4], rl[4];
                ldsm_x4(rh, kb + off);
                ldsm_x4(rl, kb + FL_BUF + off);
                mma_hf(S[2*np],     qfh[ks], rh[0], rh[2]);
                mma_hf(S[2*np + 1], qfh[ks], rh[1], rh[3]);
                mma_hf(S[2*np],     qfh[ks], rl[0], rl[2]);
                mma_hf(S[2*np + 1], qfh[ks], rl[1], rl[3]);
                mma_hf(S[2*np],     qfl[ks], rh[0], rh[2]);
                mma_hf(S[2*np + 1], qfl[ks], rh[1], rh[3]);
            }
        }

        float cm0 = -1e30f, cm1 = -1e30f;
        #pragma unroll
        for (int nt = 0; nt < 8; nt++) {
            float2 m2 = *(float2*)(smem + FL_MS + (c & 1) * 256 + (nt * 8 + (lane & 3) * 2) * 4);
            float b0 = (1.0f - m2.x) * -10000.0f;
            float b1 = (1.0f - m2.y) * -10000.0f;
            S[nt][0] = S[nt][0] * 0.125f + b0;
            S[nt][1] = S[nt][1] * 0.125f + b1;
            S[nt][2] = S[nt][2] * 0.125f + b0;
            S[nt][3] = S[nt][3] * 0.125f + b1;
            cm0 = fmaxf(cm0, fmaxf(S[nt][0], S[nt][1]));
            cm1 = fmaxf(cm1, fmaxf(S[nt][2], S[nt][3]));
        }
        #pragma unroll
        for (int o = 1; o <= 2; o <<= 1) {
            cm0 = fmaxf(cm0, __shfl_xor_sync(0xffffffffu, cm0, o));
            cm1 = fmaxf(cm1, __shfl_xor_sync(0xffffffffu, cm1, o));
        }
        float nm0 = fmaxf(runm0, cm0), nm1 = fmaxf(runm1, cm1);
        float sc0 = __expf(runm0 - nm0), sc1 = __expf(runm1 - nm1);
        float rs0 = 0.0f, rs1 = 0.0f;
        #pragma unroll
        for (int nt = 0; nt < 8; nt++) {
            S[nt][0] = __expf(S[nt][0] - nm0);
            S[nt][1] = __expf(S[nt][1] - nm0);
            S[nt][2] = __expf(S[nt][2] - nm1);
            S[nt][3] = __expf(S[nt][3] - nm1);
            rs0 += S[nt][0] + S[nt][1];
            rs1 += S[nt][2] + S[nt][3];
        }
        #pragma unroll
        for (int o = 1; o <= 2; o <<= 1) {
            rs0 += __shfl_xor_sync(0xffffffffu, rs0, o);
            rs1 += __shfl_xor_sync(0xffffffffu, rs1, o);
        }
        runl0 = runl0 * sc0 + rs0; runl1 = runl1 * sc1 + rs1;
        runm0 = nm0; runm1 = nm1;
        #pragma unroll
        for (int nt = 0; nt < 8; nt++) {
            accO[nt][0] *= sc0; accO[nt][1] *= sc0;
            accO[nt][2] *= sc1; accO[nt][3] *= sc1;
        }

        const uint32_t vb = kb + 2 * FL_BUF;
        #pragma unroll
        for (int ks2 = 0; ks2 < 4; ks2++) {
            uint32_t pah[4], pal[4];
            #pragma unroll
            for (int t = 0; t < 2; t++) {
                #pragma unroll
                for (int pr = 0; pr < 2; pr++) {
                    float x0 = S[2 * ks2 + t][pr * 2 + 0];
                    float x1 = S[2 * ks2 + t][pr * 2 + 1];
                    __half2 hb = __floats2half2_rn(x0, x1);
                    float r0 = x0 - __half2float(__low2half(hb));
                    float r1 = x1 - __half2float(__high2half(hb));
                    __half2 lb = __floats2half2_rn(r0, r1);
                    pah[t * 2 + pr] = *(uint32_t*)&hb;
                    pal[t * 2 + pr] = *(uint32_t*)&lb;
                }
            }
            #pragma unroll
            for (int dp = 0; dp < 4; dp++) {
                uint32_t off = (uint32_t)((ks2 * 16 + bkr) * FLS + dp * 16 + bnc) * 2;
                uint32_t vh4[4], vl4[4];
                ldsm_x4_t(vh4, vb + off);
                ldsm_x4_t(vl4, vb + FL_BUF + off);
                mma_hf(accO[2*dp],     pah, vh4[0], vh4[2]);
                mma_hf(accO[2*dp + 1], pah, vh4[1], vh4[3]);
                mma_hf(accO[2*dp],     pah, vl4[0], vl4[2]);
                mma_hf(accO[2*dp + 1], pah, vl4[1], vl4[3]);
                mma_hf(accO[2*dp],     pal, vh4[0], vh4[2]);
                mma_hf(accO[2*dp + 1], pal, vh4[1], vh4[3]);
            }
        }
        __syncthreads();
    }

    const float inv0 = 1.0f / runl0, inv1 = 1.0f / runl1;
    const size_t row0 = qrow0 + wid * 16 + (lane >> 2);
    #pragma unroll
    for (int nt = 0; nt < 8; nt++) {
        int col = colh + nt * 8 + (lane & 3) * 2;
        float2 w0; w0.x = accO[nt][0] * inv0; w0.y = accO[nt][1] * inv0;
        float2 w1; w1.x = accO[nt][2] * inv1; w1.y = accO[nt][3] * inv1;
        *(float2*)(out + row0 * cD + col)       = w0;
        *(float2*)(out + (row0 + 8) * cD + col) = w1;
    }
}

// ---------------- block reductions ----------------
__device__ __forceinline__ float block_sum(float v, float* sred) {
    #pragma unroll
    for (int o = 16; o > 0; o >>= 1) v += __shfl_xor_sync(0xffffffffu, v, o);
    int lane = threadIdx.x & 31, w = threadIdx.x >> 5;
    if (lane == 0) sred[w] = v;
    __syncthreads();
    if (w == 0) {
        v = (lane < (int)(blockDim.x >> 5)) ? sred[lane] : 0.0f;
        #pragma unroll
        for (int o = 16; o > 0; o >>= 1) v += __shfl_xor_sync(0xffffffffu, v, o);
        if (lane == 0) sred[0] = v;
    }
    __syncthreads();
    float r = sred[0];
    __syncthreads();
    return r;
}

// ---------------- embedding + LN0 (+ split out) ----------------
__global__ void k_embed(const int* __restrict__ ids,
                        const float* __restrict__ te, const float* __restrict__ pe,
                        const float* __restrict__ g,  const float* __restrict__ b,
                        float* __restrict__ out,
                        unsigned short* __restrict__ oh, unsigned short* __restrict__ ol) {
    __shared__ float sred[32];
    int t = blockIdx.x;
    int s = t % cS;
    int id = ids[t];
    int j4 = threadIdx.x;
    float4 a = *(const float4*)(te + (size_t)id * cD + j4 * 4);
    float4 p = *(const float4*)(pe + (size_t)s  * cD + j4 * 4);
    float x0 = a.x + p.x, x1 = a.y + p.y, x2 = a.z + p.z, x3 = a.w + p.w;

    float mu = block_sum(x0 + x1 + x2 + x3, sred) * (1.0f / cD);
    float d0 = x0 - mu, d1 = x1 - mu, d2 = x2 - mu, d3 = x3 - mu;
    float var = block_sum(d0*d0 + d1*d1 + d2*d2 + d3*d3, sred) * (1.0f / cD);
    float rs = rsqrtf(var + cEPS);

    float4 gg = *(const float4*)(g + j4 * 4);
    float4 bb = *(const float4*)(b + j4 * 4);
    float o[4];
    o[0] = d0 * rs * gg.x + bb.x;
    o[1] = d1 * rs * gg.y + bb.y;
    o[2] = d2 * rs * gg.z + bb.z;
    o[3] = d3 * rs * gg.w + bb.w;
    float4 of; of.x = o[0]; of.y = o[1]; of.z = o[2]; of.w = o[3];
    *(float4*)(out + (size_t)t * cD + j4 * 4) = of;
    unsigned short hs[4], ls[4];
    #pragma unroll
    for (int j = 0; j < 4; j++) split1(o[j], hs[j], ls[j]);
    ushort4 hv, lv;
    hv.x = hs[0]; hv.y = hs[1]; hv.z = hs[2]; hv.w = hs[3];
    lv.x = ls[0]; lv.y = ls[1]; lv.z = ls[2]; lv.w = ls[3];
    *(ushort4*)(oh + (size_t)t * cD + j4 * 4) = hv;
    *(ushort4*)(ol + (size_t)t * cD + j4 * 4) = lv;
}

// ---------------- residual add + LN (+ split out) ----------------
__global__ void k_resln(const float* __restrict__ hin, const float* __restrict__ add,
                        const float* __restrict__ g,   const float* __restrict__ b,
                        float* __restrict__ out,
                        unsigned short* __restrict__ oh, unsigned short* __restrict__ ol) {
    __shared__ float sred[32];
    int t = blockIdx.x;
    int j4 = threadIdx.x;
    float4 a = *(const float4*)(hin + (size_t)t * cD + j4 * 4);
    float4 p = *(const float4*)(add + (size_t)t * cD + j4 * 4);
    float x0 = a.x + p.x, x1 = a.y + p.y, x2 = a.z + p.z, x3 = a.w + p.w;

    float mu = block_sum(x0 + x1 + x2 + x3, sred) * (1.0f / cD);
    float d0 = x0 - mu, d1 = x1 - mu, d2 = x2 - mu, d3 = x3 - mu;
    float var = block_sum(d0*d0 + d1*d1 + d2*d2 + d3*d3, sred) * (1.0f / cD);
    float rs = rsqrtf(var + cEPS);

    float4 gg = *(const float4*)(g + j4 * 4);
    float4 bb = *(const float4*)(b + j4 * 4);
    float o[4];
    o[0] = d0 * rs * gg.x + bb.x;
    o[1] = d1 * rs * gg.y + bb.y;
    o[2] = d2 * rs * gg.z + bb.z;
    o[3] = d3 * rs * gg.w + bb.w;
    float4 of; of.x = o[0]; of.y = o[1]; of.z = o[2]; of.w = o[3];
    *(float4*)(out + (size_t)t * cD + j4 * 4) = of;
    unsigned short hs[4], ls[4];
    #pragma unroll
    for (int j = 0; j < 4; j++) split1(o[j], hs[j], ls[j]);
    ushort4 hv, lv;
    hv.x = hs[0]; hv.y = hs[1]; hv.z = hs[2]; hv.w = hs[3];
    lv.x = ls[0]; lv.y = ls[1]; lv.z = ls[2]; lv.w = ls[3];
    *(ushort4*)(oh + (size_t)t * cD + j4 * 4) = hv;
    *(ushort4*)(ol + (size_t)t * cD + j4 * 4) = lv;
}

// ---------------- launch ----------------
extern "C" void kernel_launch(void* const* d_in, const int* in_sizes, int n_in,
                              void* d_out, int out_size) {
    const int*   ids  = (const int*)  d_in[0];
    const float* mask = (const float*)d_in[1];
    const float* te   = (const float*)d_in[2];
    const float* pe   = (const float*)d_in[3];
    const float* ln0g = (const float*)d_in[4];
    const float* ln0b = (const float*)d_in[5];
    const float* Wq   = (const float*)d_in[6];
    const float* bq   = (const float*)d_in[7];
    const float* Wk   = (const float*)d_in[8];
    const float* bk   = (const float*)d_in[9];
    const float* Wv   = (const float*)d_in[10];
    const float* bv   = (const float*)d_in[11];
    const float* ln1g = (const float*)d_in[12];
    const float* ln1b = (const float*)d_in[13];
    const float* W1   = (const float*)d_in[14];
    const float* b1   = (const float*)d_in[15];
    const float* W2   = (const float*)d_in[16];
    const float* b2   = (const float*)d_in[17];
    const float* ln2g = (const float*)d_in[18];
    const float* ln2b = (const float*)d_in[19];
    const float* Wlm  = (const float*)d_in[20];
    float* out = (float*)d_out;

    float *h, *tm;
    unsigned short *wh, *wl, *ah, *al, *fh, *fl, *qh, *ql, *kh, *kl, *vh, *vl;
    cudaGetSymbolAddress((void**)&h,  g_h);
    cudaGetSymbolAddress((void**)&tm, g_t);
    cudaGetSymbolAddress((void**)&wh, g_wh);
    cudaGetSymbolAddress((void**)&wl, g_wl);
    cudaGetSymbolAddress((void**)&ah, g_ah);
    cudaGetSymbolAddress((void**)&al, g_al);
    cudaGetSymbolAddress((void**)&fh, g_fh);
    cudaGetSymbolAddress((void**)&fl, g_fl);
    cudaGetSymbolAddress((void**)&qh, g_qh);
    cudaGetSymbolAddress((void**)&ql, g_ql);
    cudaGetSymbolAddress((void**)&kh, g_kh);
    cudaGetSymbolAddress((void**)&kl, g_kl);
    cudaGetSymbolAddress((void**)&vh, g_vh);
    cudaGetSymbolAddress((void**)&vl, g_vl);

    cudaFuncSetAttribute((const void*)k_mgemm<0,3>, cudaFuncAttributeMaxDynamicSharedMemorySize, MG_SMEM);
    cudaFuncSetAttribute((const void*)k_mgemm<1,3>, cudaFuncAttributeMaxDynamicSharedMemorySize, MG_SMEM);
    cudaFuncSetAttribute((const void*)k_mgemm<2,2>, cudaFuncAttributeMaxDynamicSharedMemorySize, MG_SMEM);
    cudaFuncSetAttribute((const void*)k_mgemm<4,3>, cudaFuncAttributeMaxDynamicSharedMemorySize, MG_SMEM);
    cudaFuncSetAttribute(k_flash, cudaFuncAttributeMaxDynamicSharedMemorySize, FL_SMEM);

    // ---- weight splits: 4 launches ----
    k_split_qkv<<<(int)(cL * (size_t)cD * cD / 4 / 256), 256>>>(Wq, Wk, Wv, wh + OFF_QKV, wl + OFF_QKV);
    k_split<<<(int)(cL * W1_PL / 4 / 256), 256>>>(W1, wh + OFF_W1, wl + OFF_W1, (int)(cL * W1_PL / 4));
    k_split<<<(int)(cL * W2_PL / 4 / 256), 256>>>(W2, wh + OFF_W2, wl + OFF_W2, (int)(cL * W2_PL / 4));
    k_split<<<(int)((size_t)cD * cV / 4 / 256), 256>>>(Wlm, wh + OFF_LM, wl + OFF_LM, (int)((size_t)cD * cV / 4));

    k_embed<<<cT, 256>>>(ids, te, pe, ln0g, ln0b, h, ah, al);

    for (int l = 0; l < cL; l++) {
        const unsigned short* wqkvh = wh + OFF_QKV + (size_t)l * QKV_PL;
        const unsigned short* wqkvl = wl + OFF_QKV + (size_t)l * QKV_PL;
        const unsigned short* w1h = wh + OFF_W1 + (size_t)l * W1_PL;
        const unsigned short* w1l = wl + OFF_W1 + (size_t)l * W1_PL;
        const unsigned short* w2h = wh + OFF_W2 + (size_t)l * W2_PL;
        const unsigned short* w2l = wl + OFF_W2 + (size_t)l * W2_PL;
        size_t ovb = (size_t)l * cD;
        size_t ob1 = (size_t)l * cFF;

        k_mgemm<4,3><<<dim3(cT / 128, 3 * cD / 128), 256, MG_SMEM>>>(
            ah, al, wqkvh, wqkvl, bq + ovb, bk + ovb, bv + ovb, nullptr,
            qh, ql, kh, kl, vh, vl, cT, 3 * cD, cD);

        k_flash<<<dim3(cS / 128, cB * cH), 256, FL_SMEM>>>(qh, ql, kh, kl, vh, vl, mask, tm);

        k_resln<<<cT, 256>>>(h, tm, ln1g + ovb, ln1b + ovb, h, ah, al);

        k_mgemm<1,3><<<dim3(cT / 128, cFF / 128), 256, MG_SMEM>>>(
            ah, al, w1h, w1l, b1 + ob1, nullptr, nullptr, nullptr,
            fh, fl, nullptr, nullptr, nullptr, nullptr, cT, cFF, cD);
        k_mgemm<0,3><<<dim3(cT / 128, cD / 128), 256, MG_SMEM>>>(
            fh, fl, w2h, w2l, b2 + ovb, nullptr, nullptr, tm,
            nullptr, nullptr, nullptr, nullptr, nullptr, nullptr, cT, cD, cFF);

        k_resln<<<cT, 256>>>(h, tm, ln2g + ovb, ln2b + ovb, h, ah, al);
    }

    // LM head: terminal GEMM -> 2-term (error does not amplify through layers)
    k_mgemm<2,2><<<dim3(cT / 128, cV / 128), 256, MG_SMEM>>>(
        ah, al, wh + OFF_LM, wl + OFF_LM, nullptr, nullptr, nullptr, out,
        nullptr, nullptr, nullptr, nullptr, nullptr, nullptr, cT, cV, cD);
}

// round 17
// speedup vs baseline: 1.3896x; 1.1086x over previous
#include <cuda_runtime.h>
#include <cuda_fp16.h>
#include <math.h>
#include <stdint.h>

// ---------------- problem constants ----------------
constexpr int cL  = 12;
constexpr int cD  = 1024;
constexpr int cH  = 16;
constexpr int cDH = 64;
constexpr int cFF = 4096;
constexpr int cV  = 32000;
constexpr int cS  = 1024;
constexpr int cB  = 2;
constexpr int cT  = cB * cS;     // 2048 tokens
constexpr float cEPS = 1e-5f;

// weight-split buffer layout (concatenated, QKV packed per layer as [K=1024][N=3072])
constexpr size_t QKV_PL = (size_t)cD * 3 * cD;
constexpr size_t W1_PL  = (size_t)cD * cFF;
constexpr size_t W2_PL  = (size_t)cFF * cD;
constexpr size_t OFF_QKV = 0;
constexpr size_t OFF_W1  = (size_t)cL * QKV_PL;
constexpr size_t OFF_W2  = OFF_W1 + (size_t)cL * W1_PL;
constexpr size_t OFF_LM  = OFF_W2 + (size_t)cL * W2_PL;
constexpr size_t WTOT    = OFF_LM + (size_t)cD * cV;

// ---------------- scratch (device globals; no allocation allowed) ----------------
__device__ float g_h [cT * cD];
__device__ float g_t [cT * cD];
__device__ unsigned short g_wh[WTOT];          // weights hi (fp16 bits)
__device__ unsigned short g_wl[WTOT];          // weights lo (fp16 bits)
__device__ unsigned short g_ah[cT * cD];
__device__ unsigned short g_al[cT * cD];
__device__ unsigned short g_fh[cT * cFF];
__device__ unsigned short g_fl[cT * cFF];
__device__ unsigned short g_qh[cT * cD];
__device__ unsigned short g_ql[cT * cD];
__device__ unsigned short g_kh[cT * cD];
__device__ unsigned short g_kl[cT * cD];
__device__ unsigned short g_vh[cT * cD];
__device__ unsigned short g_vl[cT * cD];

// ================= PTX helpers =================
__device__ __forceinline__ uint32_t smem_u32(const void* p) {
    uint32_t a;
    asm("{ .reg .u64 t; cvta.to.shared.u64 t, %1; cvt.u32.u64 %0, t; }" : "=r"(a) : "l"(p));
    return a;
}
#define CPA16(smem, g) \
    asm volatile("cp.async.cg.shared.global [%0], [%1], 16;" \
        :: "r"(smem), "l"(__cvta_generic_to_global((const void*)(g))) : "memory")
#define CP_COMMIT() asm volatile("cp.async.commit_group;" ::: "memory")
#define CP_WAIT(n)  asm volatile("cp.async.wait_group %0;" :: "n"(n) : "memory")

__device__ __forceinline__ void ldsm_x4(uint32_t* r, uint32_t addr) {
    asm volatile("ldmatrix.sync.aligned.m8n8.x4.shared.b16 {%0,%1,%2,%3}, [%4];"
        : "=r"(r[0]), "=r"(r[1]), "=r"(r[2]), "=r"(r[3]) : "r"(addr));
}
__device__ __forceinline__ void ldsm_x4_t(uint32_t* r, uint32_t addr) {
    asm volatile("ldmatrix.sync.aligned.m8n8.x4.trans.shared.b16 {%0,%1,%2,%3}, [%4];"
        : "=r"(r[0]), "=r"(r[1]), "=r"(r[2]), "=r"(r[3]) : "r"(addr));
}
// fp16 inputs, fp32 accumulator
__device__ __forceinline__ void mma_hf(float* c, const uint32_t* a, uint32_t b0, uint32_t b1) {
    asm volatile(
        "mma.sync.aligned.m16n8k16.row.col.f32.f16.f16.f32 "
        "{%0,%1,%2,%3}, {%4,%5,%6,%7}, {%8,%9}, {%0,%1,%2,%3};"
        : "+f"(c[0]), "+f"(c[1]), "+f"(c[2]), "+f"(c[3])
        : "r"(a[0]), "r"(a[1]), "r"(a[2]), "r"(a[3]), "r"(b0), "r"(b1));
}
__device__ __forceinline__ void split1(float x, unsigned short& h, unsigned short& l) {
    __half hb = __float2half_rn(x);
    __half lb = __float2half_rn(x - __half2float(hb));
    h = __half_as_ushort(hb);
    l = __half_as_ushort(lb);
}

// ---------------- split fp32 -> hi/lo fp16 (weights) ----------------
__global__ void k_split(const float* __restrict__ src, unsigned short* __restrict__ hi,
                        unsigned short* __restrict__ lo, int n4) {
    int i = blockIdx.x * blockDim.x + threadIdx.x;
    if (i >= n4) return;
    float4 v = ((const float4*)src)[i];
    float f[4] = {v.x, v.y, v.z, v.w};
    unsigned short hs[4], ls[4];
    #pragma unroll
    for (int j = 0; j < 4; j++) split1(f[j], hs[j], ls[j]);
    ushort4 h, l;
    h.x = hs[0]; h.y = hs[1]; h.z = hs[2]; h.w = hs[3];
    l.x = ls[0]; l.y = ls[1]; l.z = ls[2]; l.w = ls[3];
    ((ushort4*)hi)[i] = h;
    ((ushort4*)lo)[i] = l;
}

__global__ void k_split_qkv(const float* __restrict__ wq, const float* __restrict__ wk,
                            const float* __restrict__ wv,
                            unsigned short* __restrict__ hi, unsigned short* __restrict__ lo) {
    int i = blockIdx.x * blockDim.x + threadIdx.x;
    if (i >= (int)(cL * (size_t)cD * cD / 4)) return;
    int l = i >> 18;
    int rem = i & 0x3FFFF;
    int kk = rem >> 8;
    int n4 = rem & 255;
    size_t dbase = (size_t)l * (QKV_PL / 4) + (size_t)kk * 768 + n4;
    const float* srcs[3] = {wq, wk, wv};
    #pragma unroll
    for (int sel = 0; sel < 3; sel++) {
        float4 v = ((const float4*)srcs[sel])[i];
        float f[4] = {v.x, v.y, v.z, v.w};
        unsigned short hs[4], ls[4];
        #pragma unroll
        for (int j = 0; j < 4; j++) split1(f[j], hs[j], ls[j]);
        ushort4 h, lw;
        h.x = hs[0]; h.y = hs[1]; h.z = hs[2]; h.w = hs[3];
        lw.x = ls[0]; lw.y = ls[1]; lw.z = ls[2]; lw.w = ls[3];
        ((ushort4*)hi)[dbase + sel * 256] = h;
        ((ushort4*)lo)[dbase + sel * 256] = lw;
    }
}

// ================= tensor-core GEMM (fp16 split, R8 structure) =====
// CTA 128x128x32, 256 threads = 8 warps (2M x 4N), warp tile 64x32, 3-stage, 2 CTA/SM.
// TERMS: 3 = AhBh + AhBl + AlBh; 2 = AhBh + AhBl (drops A-lo term)
// EPI: 0 = +bias -> fp32 C, 1 = +bias+gelu -> split Ch0/Cl0, 2 = plain -> fp32 C,
//      4 = QKV fused: output dispatch by n0>>10, out stride 1024
constexpr int A_STRIDE = 40;
constexpr int B_STRIDE = 136;
constexpr int A_SZ  = 128 * A_STRIDE * 2;
constexpr int B_SZ  = 32  * B_STRIDE * 2;
constexpr int STG   = 2 * A_SZ + 2 * B_SZ;           // 37888
constexpr int MG_SMEM = 3 * STG;                     // 113664 -> 2 CTAs/SM

template <int EPI, int TERMS>
__global__ void __launch_bounds__(256, 2) k_mgemm(
        const unsigned short* __restrict__ Ahg, const unsigned short* __restrict__ Alg,
        const unsigned short* __restrict__ Bhg, const unsigned short* __restrict__ Blg,
        const float* __restrict__ bias0, const float* __restrict__ bias1,
        const float* __restrict__ bias2, float* __restrict__ C,
        unsigned short* __restrict__ Ch0, unsigned short* __restrict__ Cl0,
        unsigned short* __restrict__ Ch1, unsigned short* __restrict__ Cl1,
        unsigned short* __restrict__ Ch2, unsigned short* __restrict__ Cl2,
        int M, int N, int K) {
    extern __shared__ char smem[];
    const uint32_t sb = smem_u32(smem);
    const int tid = threadIdx.x;
    const int lane = tid & 31, wid = tid >> 5;
    const int wm = (wid >> 2) * 64;
    const int wn = (wid & 3) * 32;
    const int m0 = blockIdx.x * 128, n0 = blockIdx.y * 128;
    const int nch = K >> 5;

    const int ar = tid >> 1;
    const int aseg = (tid & 1) * 16;
    const int br = tid >> 3;
    const int bseg = (tid & 7) * 16;

    auto issue = [&](int c) {
        const int st = c % 3;
        const int k0 = c << 5;
        const uint32_t s = sb + st * STG;
        const size_t ago = (size_t)(m0 + ar) * K + k0 + aseg;
        const size_t bgo = (size_t)(k0 + br) * N + n0 + bseg;
        const uint32_t asm_off = s + (uint32_t)(ar * A_STRIDE + aseg) * 2;
        const uint32_t bsm_off = s + 2 * A_SZ + (uint32_t)(br * B_STRIDE + bseg) * 2;
        #pragma unroll
        for (int j = 0; j < 2; j++) {
            CPA16(asm_off + j * 16,          Ahg + ago + j * 8);
            CPA16(bsm_off + j * 16,          Bhg + bgo + j * 8);
            CPA16(bsm_off + B_SZ + j * 16,   Blg + bgo + j * 8);
            if (TERMS == 3) {
                CPA16(asm_off + A_SZ + j * 16, Alg + ago + j * 8);
            }
        }
    };

    const int alr = (lane & 7) + ((lane >> 3) & 1) * 8;
    const int alc = (lane >> 4) * 8;
    const uint32_t a_lane = (uint32_t)(alr * A_STRIDE + alc) * 2;
    const int bkr = ((lane >> 4) & 1) * 8 + (lane & 7);
    const int bnc = ((lane >> 3) & 1) * 8;
    const uint32_t b_lane = (uint32_t)(bkr * B_STRIDE + bnc) * 2;

    float acc[4][4][4] = {};

    issue(0); CP_COMMIT();
    issue(1); CP_COMMIT();

    for (int c = 0; c < nch; c++) {
        if (c + 1 < nch) CP_WAIT(1);
        else             CP_WAIT(0);
        __syncthreads();
        if (c + 2 < nch) { issue(c + 2); CP_COMMIT(); }

        const uint32_t s  = sb + (c % 3) * STG;
        const uint32_t ah_b = s + (uint32_t)(wm * A_STRIDE) * 2 + a_lane;
        const uint32_t al_b = ah_b + A_SZ;
        const uint32_t bh_b = s + 2 * A_SZ + (uint32_t)wn * 2 + b_lane;
        const uint32_t bl_b = bh_b + B_SZ;

        #pragma unroll
        for (int ks = 0; ks < 2; ks++) {
            const uint32_t ak = (uint32_t)(ks * 16) * 2;
            const uint32_t bk = (uint32_t)(ks * 16 * B_STRIDE) * 2;

            uint32_t ah[4][4];
            #pragma unroll
            for (int mt = 0; mt < 4; mt++)
                ldsm_x4(ah[mt], ah_b + ak + (uint32_t)(mt * 16 * A_STRIDE) * 2);
            uint32_t bh0[4], bh1[4];
            #pragma unroll
            for (int p = 0; p < 2; p++) {
                uint32_t r[4];
                ldsm_x4_t(r, bh_b + bk + (uint32_t)(p * 16) * 2);
                bh0[p * 2] = r[0]; bh0[p * 2 + 1] = r[1];
                bh1[p * 2] = r[2]; bh1[p * 2 + 1] = r[3];
            }
            // Ah * Bh
            #pragma unroll
            for (int mt = 0; mt < 4; mt++)
                #pragma unroll
                for (int nt = 0; nt < 4; nt++)
                    mma_hf(acc[mt][nt], ah[mt], bh0[nt], bh1[nt]);

            // Ah * Bl
            {
                uint32_t bl0[4], bl1[4];
                #pragma unroll
                for (int p = 0; p < 2; p++) {
                    uint32_t r[4];
                    ldsm_x4_t(r, bl_b + bk + (uint32_t)(p * 16) * 2);
                    bl0[p * 2] = r[0]; bl0[p * 2 + 1] = r[1];
                    bl1[p * 2] = r[2]; bl1[p * 2 + 1] = r[3];
                }
                #pragma unroll
                for (int mt = 0; mt < 4; mt++)
                    #pragma unroll
                    for (int nt = 0; nt < 4; nt++)
                        mma_hf(acc[mt][nt], ah[mt], bl0[nt], bl1[nt]);
            }
            // Al * Bh
            if (TERMS == 3) {
                uint32_t al[4];
                #pragma unroll
                for (int mt = 0; mt < 4; mt++) {
                    ldsm_x4(al, al_b + ak + (uint32_t)(mt * 16 * A_STRIDE) * 2);
                    #pragma unroll
                    for (int nt = 0; nt < 4; nt++)
                        mma_hf(acc[mt][nt], al, bh0[nt], bh1[nt]);
                }
            }
        }
    }

    // ---- epilogue ----
    const int erow = lane >> 2;
    const int ecol = (lane & 3) * 2;

    const float* bias = bias0;
    unsigned short* OH = Ch0;
    unsigned short* OL = Cl0;
    int outN = N, nbase = n0;
    if (EPI == 4) {
        const int sel = n0 >> 10;
        bias = (sel == 0) ? bias0 : ((sel == 1) ? bias1 : bias2);
        OH   = (sel == 0) ? Ch0   : ((sel == 1) ? Ch1   : Ch2);
        OL   = (sel == 0) ? Cl0   : ((sel == 1) ? Cl1   : Cl2);
        outN = 1024;
        nbase = n0 & 1023;
    }

    #pragma unroll
    for (int mt = 0; mt < 4; mt++) {
        #pragma unroll
        for (int nt = 0; nt < 4; nt++) {
            const int row = m0 + wm + mt * 16 + erow;
            const int col = nbase + wn + nt * 8 + ecol;
            float v[4] = {acc[mt][nt][0], acc[mt][nt][1], acc[mt][nt][2], acc[mt][nt][3]};
            if (EPI != 2) {
                float b0 = bias[col], b1 = bias[col + 1];
                v[0] += b0; v[1] += b1; v[2] += b0; v[3] += b1;
            }
            if (EPI == 1) {
                #pragma unroll
                for (int j = 0; j < 4; j++)
                    v[j] = 0.5f * v[j] * (1.0f + erff(v[j] * 0.70710678118654752f));
            }
            if (EPI == 0 || EPI == 2) {
                float2 w0; w0.x = v[0]; w0.y = v[1];
                float2 w1; w1.x = v[2]; w1.y = v[3];
                *(float2*)(C + (size_t)row * outN + col)       = w0;
                *(float2*)(C + (size_t)(row + 8) * outN + col) = w1;
            } else {
                unsigned short hs[4], ls[4];
                #pragma unroll
                for (int j = 0; j < 4; j++) split1(v[j], hs[j], ls[j]);
                ushort2 h0, h1, l0, l1;
                h0.x = hs[0]; h0.y = hs[1]; h1.x = hs[2]; h1.y = hs[3];
                l0.x = ls[0]; l0.y = ls[1]; l1.x = ls[2]; l1.y = ls[3];
                *(ushort2*)(OH + (size_t)row * outN + col)       = h0;
                *(ushort2*)(OH + (size_t)(row + 8) * outN + col) = h1;
                *(ushort2*)(OL + (size_t)row * outN + col)       = l0;
                *(ushort2*)(OL + (size_t)(row + 8) * outN + col) = l1;
            }
        }
    }
}

// ================= fused flash attention (fp16 3-term, fp32 acc) ==========
constexpr int FLS    = 72;
constexpr int FL_QL  = 128 * FLS * 2;
constexpr int FL_ST  = 2 * FL_QL;
constexpr int FL_BUF = 64 * FLS * 2;
constexpr int FL_STSZ = 4 * FL_BUF;
constexpr int FL_MS  = FL_ST + 2 * FL_STSZ;
constexpr int FL_SMEM = FL_MS + 2 * 64 * 4;

__global__ void __launch_bounds__(256) k_flash(
        const unsigned short* __restrict__ Qh, const unsigned short* __restrict__ Ql,
        const unsigned short* __restrict__ Kh, const unsigned short* __restrict__ Kl,
        const unsigned short* __restrict__ Vh, const unsigned short* __restrict__ Vl,
        const float* __restrict__ mask, float* __restrict__ out) {
    extern __shared__ char smem[];
    const uint32_t sb = smem_u32(smem);
    const int tid = threadIdx.x, lane = tid & 31, wid = tid >> 5;
    const int qt = blockIdx.x, bh = blockIdx.y, b = bh >> 4, h = bh & 15;
    const size_t qrow0 = (size_t)(b * cS + qt * 128);
    const int colh = h * 64;

    for (int i = tid; i < 1024; i += 256) {
        int r = i >> 3, sg = i & 7;
        size_t g = (qrow0 + r) * cD + colh + sg * 8;
        uint32_t s = sb + (uint32_t)(r * FLS + sg * 8) * 2;
        CPA16(s, Qh + g);
        CPA16(s + FL_QL, Ql + g);
    }
    auto issueKV = [&](int c) {
        int st = c & 1;
        uint32_t base = sb + FL_ST + st * FL_STSZ;
        for (int i = tid; i < 512; i += 256) {
            int r = i >> 3, sg = i & 7;
            size_t g = ((size_t)(b * cS + c * 64 + r)) * cD + colh + sg * 8;
            uint32_t s = base + (uint32_t)(r * FLS + sg * 8) * 2;
            CPA16(s,              Kh + g);
            CPA16(s + FL_BUF,     Kl + g);
            CPA16(s + 2 * FL_BUF, Vh + g);
            CPA16(s + 3 * FL_BUF, Vl + g);
        }
        if (tid < 16)
            CPA16(sb + FL_MS + st * 256 + tid * 16, mask + b * cS + c * 64 + tid * 4);
    };
    issueKV(0); CP_COMMIT();

    const int alr = (lane & 7) + ((lane >> 3) & 1) * 8;
    const int alc = (lane >> 4) * 8;
    const int bkr = ((lane >> 4) & 1) * 8 + (lane & 7);
    const int bnc = ((lane >> 3) & 1) * 8;

    uint32_t qfh[4][4], qfl[4][4];
    float accO[8][4] = {};
    float runm0 = -1e30f, runm1 = -1e30f, runl0 = 0.0f, runl1 = 0.0f;

    for (int c = 0; c < 16; c++) {
        if (c + 1 < 16) { issueKV(c + 1); CP_COMMIT(); CP_WAIT(1); }
        else            { CP_WAIT(0); }
        __syncthreads();
        if (c == 0) {
            uint32_t qb = sb + (uint32_t)((wid * 16 + alr) * FLS + alc) * 2;
            #pragma unroll
            for (int ks = 0; ks < 4; ks++) {
                ldsm_x4(qfh[ks], qb + ks * 32);
                ldsm_x4(qfl[ks], qb + FL_QL + ks * 32);
            }
        }
        const uint32_t kb = sb + FL_ST + (c & 1) * FL_STSZ;

        float S[8][4] = {};
        #pragma unroll
        for (int ks = 0; ks < 4; ks++) {
            #pragma unroll
            for (int np = 0; np < 4; np++) {
                uint32_t off = (uint32_t)((np * 16 + alr) * FLS + ks * 16 + alc) * 2;
                uint32_t rh[4], rl[4];
                ldsm_x4(rh, kb + off);
                ldsm_x4(rl, kb + FL_BUF + off);
                mma_hf(S[2*np],     qfh[ks], rh[0], rh[2]);
                mma_hf(S[2*np + 1], qfh[ks], rh[1], rh[3]);
                mma_hf(S[2*np],     qfh[ks], rl[0], rl[2]);
                mma_hf(S[2*np + 1], qfh[ks], rl[1], rl[3]);
                mma_hf(S[2*np],     qfl[ks], rh[0], rh[2]);
                mma_hf(S[2*np + 1], qfl[ks], rh[1], rh[3]);
            }
        }

        float cm0 = -1e30f, cm1 = -1e30f;
        #pragma unroll
        for (int nt = 0; nt < 8; nt++) {
            float2 m2 = *(float2*)(smem + FL_MS + (c & 1) * 256 + (nt * 8 + (lane & 3) * 2) * 4);
            float b0 = (1.0f - m2.x) * -10000.0f;
            float b1 = (1.0f - m2.y) * -10000.0f;
            S[nt][0] = S[nt][0] * 0.125f + b0;
            S[nt][1] = S[nt][1] * 0.125f + b1;
            S[nt][2] = S[nt][2] * 0.125f + b0;
            S[nt][3] = S[nt][3] * 0.125f + b1;
            cm0 = fmaxf(cm0, fmaxf(S[nt][0], S[nt][1]));
            cm1 = fmaxf(cm1, fmaxf(S[nt][2], S[nt][3]));
        }
        #pragma unroll
        for (int o = 1; o <= 2; o <<= 1) {
            cm0 = fmaxf(cm0, __shfl_xor_sync(0xffffffffu, cm0, o));
            cm1 = fmaxf(cm1, __shfl_xor_sync(0xffffffffu, cm1, o));
        }
        float nm0 = fmaxf(runm0, cm0), nm1 = fmaxf(runm1, cm1);
        float sc0 = __expf(runm0 - nm0), sc1 = __expf(runm1 - nm1);
        float rs0 = 0.0f, rs1 = 0.0f;
        #pragma unroll
        for (int nt = 0; nt < 8; nt++) {
            S[nt][0] = __expf(S[nt][0] - nm0);
            S[nt][1] = __expf(S[nt][1] - nm0);
            S[nt][2] = __expf(S[nt][2] - nm1);
            S[nt][3] = __expf(S[nt][3] - nm1);
            rs0 += S[nt][0] + S[nt][1];
            rs1 += S[nt][2] + S[nt][3];
        }
        #pragma unroll
        for (int o = 1; o <= 2; o <<= 1) {
            rs0 += __shfl_xor_sync(0xffffffffu, rs0, o);
            rs1 += __shfl_xor_sync(0xffffffffu, rs1, o);
        }
        runl0 = runl0 * sc0 + rs0; runl1 = runl1 * sc1 + rs1;
        runm0 = nm0; runm1 = nm1;
        #pragma unroll
        for (int nt = 0; nt < 8; nt++) {
            accO[nt][0] *= sc0; accO[nt][1] *= sc0;
            accO[nt][2] *= sc1; accO[nt][3] *= sc1;
        }

        const uint32_t vb = kb + 2 * FL_BUF;
        #pragma unroll
        for (int ks2 = 0; ks2 < 4; ks2++) {
            uint32_t pah[4], pal[4];
            #pragma unroll
            for (int t = 0; t < 2; t++) {
                #pragma unroll
                for (int pr = 0; pr < 2; pr++) {
                    float x0 = S[2 * ks2 + t][pr * 2 + 0];
                    float x1 = S[2 * ks2 + t][pr * 2 + 1];
                    __half2 hb = __floats2half2_rn(x0, x1);
                    float r0 = x0 - __half2float(__low2half(hb));
                    float r1 = x1 - __half2float(__high2half(hb));
                    __half2 lb = __floats2half2_rn(r0, r1);
                    pah[t * 2 + pr] = *(uint32_t*)&hb;
                    pal[t * 2 + pr] = *(uint32_t*)&lb;
                }
            }
            #pragma unroll
            for (int dp = 0; dp < 4; dp++) {
                uint32_t off = (uint32_t)((ks2 * 16 + bkr) * FLS + dp * 16 + bnc) * 2;
                uint32_t vh4[4], vl4[4];
                ldsm_x4_t(vh4, vb + off);
                ldsm_x4_t(vl4, vb + FL_BUF + off);
                mma_hf(accO[2*dp],     pah, vh4[0], vh4[2]);
                mma_hf(accO[2*dp + 1], pah, vh4[1], vh4[3]);
                mma_hf(accO[2*dp],     pah, vl4[0], vl4[2]);
                mma_hf(accO[2*dp + 1], pah, vl4[1], vl4[3]);
                mma_hf(accO[2*dp],     pal, vh4[0], vh4[2]);
                mma_hf(accO[2*dp + 1], pal, vh4[1], vh4[3]);
            }
        }
        __syncthreads();
    }

    const float inv0 = 1.0f / runl0, inv1 = 1.0f / runl1;
    const size_t row0 = qrow0 + wid * 16 + (lane >> 2);
    #pragma unroll
    for (int nt = 0; nt < 8; nt++) {
        int col = colh + nt * 8 + (lane & 3) * 2;
        float2 w0; w0.x = accO[nt][0] * inv0; w0.y = accO[nt][1] * inv0;
        float2 w1; w1.x = accO[nt][2] * inv1; w1.y = accO[nt][3] * inv1;
        *(float2*)(out + row0 * cD + col)       = w0;
        *(float2*)(out + (row0 + 8) * cD + col) = w1;
    }
}

// ---------------- block reductions ----------------
__device__ __forceinline__ float block_sum(float v, float* sred) {
    #pragma unroll
    for (int o = 16; o > 0; o >>= 1) v += __shfl_xor_sync(0xffffffffu, v, o);
    int lane = threadIdx.x & 31, w = threadIdx.x >> 5;
    if (lane == 0) sred[w] = v;
    __syncthreads();
    if (w == 0) {
        v = (lane < (int)(blockDim.x >> 5)) ? sred[lane] : 0.0f;
        #pragma unroll
        for (int o = 16; o > 0; o >>= 1) v += __shfl_xor_sync(0xffffffffu, v, o);
        if (lane == 0) sred[0] = v;
    }
    __syncthreads();
    float r = sred[0];
    __syncthreads();
    return r;
}

// ---------------- embedding + LN0 (+ split out) ----------------
__global__ void k_embed(const int* __restrict__ ids,
                        const float* __restrict__ te, const float* __restrict__ pe,
                        const float* __restrict__ g,  const float* __restrict__ b,
                        float* __restrict__ out,
                        unsigned short* __restrict__ oh, unsigned short* __restrict__ ol) {
    __shared__ float sred[32];
    int t = blockIdx.x;
    int s = t % cS;
    int id = ids[t];
    int j4 = threadIdx.x;
    float4 a = *(const float4*)(te + (size_t)id * cD + j4 * 4);
    float4 p = *(const float4*)(pe + (size_t)s  * cD + j4 * 4);
    float x0 = a.x + p.x, x1 = a.y + p.y, x2 = a.z + p.z, x3 = a.w + p.w;

    float mu = block_sum(x0 + x1 + x2 + x3, sred) * (1.0f / cD);
    float d0 = x0 - mu, d1 = x1 - mu, d2 = x2 - mu, d3 = x3 - mu;
    float var = block_sum(d0*d0 + d1*d1 + d2*d2 + d3*d3, sred) * (1.0f / cD);
    float rs = rsqrtf(var + cEPS);

    float4 gg = *(const float4*)(g + j4 * 4);
    float4 bb = *(const float4*)(b + j4 * 4);
    float o[4];
    o[0] = d0 * rs * gg.x + bb.x;
    o[1] = d1 * rs * gg.y + bb.y;
    o[2] = d2 * rs * gg.z + bb.z;
    o[3] = d3 * rs * gg.w + bb.w;
    float4 of; of.x = o[0]; of.y = o[1]; of.z = o[2]; of.w = o[3];
    *(float4*)(out + (size_t)t * cD + j4 * 4) = of;
    unsigned short hs[4], ls[4];
    #pragma unroll
    for (int j = 0; j < 4; j++) split1(o[j], hs[j], ls[j]);
    ushort4 hv, lv;
    hv.x = hs[0]; hv.y = hs[1]; hv.z = hs[2]; hv.w = hs[3];
    lv.x = ls[0]; lv.y = ls[1]; lv.z = ls[2]; lv.w = ls[3];
    *(ushort4*)(oh + (size_t)t * cD + j4 * 4) = hv;
    *(ushort4*)(ol + (size_t)t * cD + j4 * 4) = lv;
}

// ---------------- residual add + LN (+ split out) ----------------
__global__ void k_resln(const float* __restrict__ hin, const float* __restrict__ add,
                        const float* __restrict__ g,   const float* __restrict__ b,
                        float* __restrict__ out,
                        unsigned short* __restrict__ oh, unsigned short* __restrict__ ol) {
    __shared__ float sred[32];
    int t = blockIdx.x;
    int j4 = threadIdx.x;
    float4 a = *(const float4*)(hin + (size_t)t * cD + j4 * 4);
    float4 p = *(const float4*)(add + (size_t)t * cD + j4 * 4);
    float x0 = a.x + p.x, x1 = a.y + p.y, x2 = a.z + p.z, x3 = a.w + p.w;

    float mu = block_sum(x0 + x1 + x2 + x3, sred) * (1.0f / cD);
    float d0 = x0 - mu, d1 = x1 - mu, d2 = x2 - mu, d3 = x3 - mu;
    float var = block_sum(d0*d0 + d1*d1 + d2*d2 + d3*d3, sred) * (1.0f / cD);
    float rs = rsqrtf(var + cEPS);

    float4 gg = *(const float4*)(g + j4 * 4);
    float4 bb = *(const float4*)(b + j4 * 4);
    float o[4];
    o[0] = d0 * rs * gg.x + bb.x;
    o[1] = d1 * rs * gg.y + bb.y;
    o[2] = d2 * rs * gg.z + bb.z;
    o[3] = d3 * rs * gg.w + bb.w;
    float4 of; of.x = o[0]; of.y = o[1]; of.z = o[2]; of.w = o[3];
    *(float4*)(out + (size_t)t * cD + j4 * 4) = of;
    unsigned short hs[4], ls[4];
    #pragma unroll
    for (int j = 0; j < 4; j++) split1(o[j], hs[j], ls[j]);
    ushort4 hv, lv;
    hv.x = hs[0]; hv.y = hs[1]; hv.z = hs[2]; hv.w = hs[3];
    lv.x = ls[0]; lv.y = ls[1]; lv.z = ls[2]; lv.w = ls[3];
    *(ushort4*)(oh + (size_t)t * cD + j4 * 4) = hv;
    *(ushort4*)(ol + (size_t)t * cD + j4 * 4) = lv;
}

// ---------------- launch ----------------
extern "C" void kernel_launch(void* const* d_in, const int* in_sizes, int n_in,
                              void* d_out, int out_size) {
    const int*   ids  = (const int*)  d_in[0];
    const float* mask = (const float*)d_in[1];
    const float* te   = (const float*)d_in[2];
    const float* pe   = (const float*)d_in[3];
    const float* ln0g = (const float*)d_in[4];
    const float* ln0b = (const float*)d_in[5];
    const float* Wq   = (const float*)d_in[6];
    const float* bq   = (const float*)d_in[7];
    const float* Wk   = (const float*)d_in[8];
    const float* bk   = (const float*)d_in[9];
    const float* Wv   = (const float*)d_in[10];
    const float* bv   = (const float*)d_in[11];
    const float* ln1g = (const float*)d_in[12];
    const float* ln1b = (const float*)d_in[13];
    const float* W1   = (const float*)d_in[14];
    const float* b1   = (const float*)d_in[15];
    const float* W2   = (const float*)d_in[16];
    const float* b2   = (const float*)d_in[17];
    const float* ln2g = (const float*)d_in[18];
    const float* ln2b = (const float*)d_in[19];
    const float* Wlm  = (const float*)d_in[20];
    float* out = (float*)d_out;

    float *h, *tm;
    unsigned short *wh, *wl, *ah, *al, *fh, *fl, *qh, *ql, *kh, *kl, *vh, *vl;
    cudaGetSymbolAddress((void**)&h,  g_h);
    cudaGetSymbolAddress((void**)&tm, g_t);
    cudaGetSymbolAddress((void**)&wh, g_wh);
    cudaGetSymbolAddress((void**)&wl, g_wl);
    cudaGetSymbolAddress((void**)&ah, g_ah);
    cudaGetSymbolAddress((void**)&al, g_al);
    cudaGetSymbolAddress((void**)&fh, g_fh);
    cudaGetSymbolAddress((void**)&fl, g_fl);
    cudaGetSymbolAddress((void**)&qh, g_qh);
    cudaGetSymbolAddress((void**)&ql, g_ql);
    cudaGetSymbolAddress((void**)&kh, g_kh);
    cudaGetSymbolAddress((void**)&kl, g_kl);
    cudaGetSymbolAddress((void**)&vh, g_vh);
    cudaGetSymbolAddress((void**)&vl, g_vl);

    cudaFuncSetAttribute((const void*)k_mgemm<0,3>, cudaFuncAttributeMaxDynamicSharedMemorySize, MG_SMEM);
    cudaFuncSetAttribute((const void*)k_mgemm<0,2>, cudaFuncAttributeMaxDynamicSharedMemorySize, MG_SMEM);
    cudaFuncSetAttribute((const void*)k_mgemm<1,3>, cudaFuncAttributeMaxDynamicSharedMemorySize, MG_SMEM);
    cudaFuncSetAttribute((const void*)k_mgemm<2,2>, cudaFuncAttributeMaxDynamicSharedMemorySize, MG_SMEM);
    cudaFuncSetAttribute((const void*)k_mgemm<4,3>, cudaFuncAttributeMaxDynamicSharedMemorySize, MG_SMEM);
    cudaFuncSetAttribute(k_flash, cudaFuncAttributeMaxDynamicSharedMemorySize, FL_SMEM);

    // ---- weight splits: 4 launches ----
    k_split_qkv<<<(int)(cL * (size_t)cD * cD / 4 / 256), 256>>>(Wq, Wk, Wv, wh + OFF_QKV, wl + OFF_QKV);
    k_split<<<(int)(cL * W1_PL / 4 / 256), 256>>>(W1, wh + OFF_W1, wl + OFF_W1, (int)(cL * W1_PL / 4));
    k_split<<<(int)(cL * W2_PL / 4 / 256), 256>>>(W2, wh + OFF_W2, wl + OFF_W2, (int)(cL * W2_PL / 4));
    k_split<<<(int)((size_t)cD * cV / 4 / 256), 256>>>(Wlm, wh + OFF_LM, wl + OFF_LM, (int)((size_t)cD * cV / 4));

    k_embed<<<cT, 256>>>(ids, te, pe, ln0g, ln0b, h, ah, al);

    for (int l = 0; l < cL; l++) {
        const unsigned short* wqkvh = wh + OFF_QKV + (size_t)l * QKV_PL;
        const unsigned short* wqkvl = wl + OFF_QKV + (size_t)l * QKV_PL;
        const unsigned short* w1h = wh + OFF_W1 + (size_t)l * W1_PL;
        const unsigned short* w1l = wl + OFF_W1 + (size_t)l * W1_PL;
        const unsigned short* w2h = wh + OFF_W2 + (size_t)l * W2_PL;
        const unsigned short* w2l = wl + OFF_W2 + (size_t)l * W2_PL;
        size_t ovb = (size_t)l * cD;
        size_t ob1 = (size_t)l * cFF;

        k_mgemm<4,3><<<dim3(cT / 128, 3 * cD / 128), 256, MG_SMEM>>>(
            ah, al, wqkvh, wqkvl, bq + ovb, bk + ovb, bv + ovb, nullptr,
            qh, ql, kh, kl, vh, vl, cT, 3 * cD, cD);

        k_flash<<<dim3(cS / 128, cB * cH), 256, FL_SMEM>>>(qh, ql, kh, kl, vh, vl, mask, tm);

        k_resln<<<cT, 256>>>(h, tm, ln1g + ovb, ln1b + ovb, h, ah, al);

        k_mgemm<1,3><<<dim3(cT / 128, cFF / 128), 256, MG_SMEM>>>(
            ah, al, w1h, w1l, b1 + ob1, nullptr, nullptr, nullptr,
            fh, fl, nullptr, nullptr, nullptr, nullptr, cT, cFF, cD);
        // FFN2: 2-term (drop hidden-lo term; mid-stack damping measured via this round)
        k_mgemm<0,2><<<dim3(cT / 128, cD / 128), 256, MG_SMEM>>>(
            fh, fl, w2h, w2l, b2 + ovb, nullptr, nullptr, tm,
            nullptr, nullptr, nullptr, nullptr, nullptr, nullptr, cT, cD, cFF);

        k_resln<<<cT, 256>>>(h, tm, ln2g + ovb, ln2b + ovb, h, ah, al);
    }

    // LM head: terminal GEMM -> 2-term
    k_mgemm<2,2><<<dim3(cT / 128, cV / 128), 256, MG_SMEM>>>(
        ah, al, wh + OFF_LM, wl + OFF_LM, nullptr, nullptr, nullptr, out,
        nullptr, nullptr, nullptr, nullptr, nullptr, nullptr, cT, cV, cD);
}